// round 1
// baseline (speedup 1.0000x reference)
#include <cuda_runtime.h>
#include <math.h>

#define BATCH  8192
#define LATENT 256
#define CD     128
#define UDIM   32
#define NY     50

#define BM 128
#define BN 128
#define BK 16
#define TM 8
#define TN 8
#define NTHREADS 256

// ---------------- scratch (static device globals; no allocation) ----------------
__device__ float g_x1[BATCH * LATENT];
__device__ float g_x2[BATCH * LATENT];
__device__ float g_hz[BATCH * LATENT];
__device__ float g_ao[BATCH * LATENT];      // [:,0:128]=alpha pre-act, [:,128:256]=omega
__device__ float g_zincr_r[BATCH * CD];
__device__ float g_zincr_i[BATCH * CD];
__device__ float g_ytr[BATCH * NY];
__device__ float g_yti[BATCH * NY];
__device__ float g_ytd[BATCH * NY];

// ---------------------------------------------------------------------------
// One fused GEMM kernel, C = A[M,K] @ W[N,K]^T (+bias), with mode-specific
// epilogue:
//   MODE 0: A = concat(zt, ut, dt) (K=289), epilogue BN(eval)+ReLU
//   MODE 1: plain A, epilogue BN(eval)+ReLU
//   MODE 2: plain A, epilogue +bias, store
//   MODE 3: epilogue +bias then contract groups of 32 cols with ut*dt  (Bt)
//   MODE 4: epilogue +bias then contract all 128 cols with z_next part (Ct)
//   MODE 5: like MODE 3 but with N bounds checks (Dt, N=1600)
// Thread layout: 16x16 threads, each owns an 8x8 microtile.
// ---------------------------------------------------------------------------
template <int MODE>
__global__ __launch_bounds__(NTHREADS)
void gemm_fused(const float* __restrict__ A,
                int K,
                const float* __restrict__ W,
                int N,
                const float* __restrict__ bias,
                const float* __restrict__ p0,   // ut (3/5/0) | zv base (4)
                const float* __restrict__ p1,   // dt (3/5/0)
                const float* __restrict__ p2,   // bn gamma (0/1)
                const float* __restrict__ p3,   // bn beta  (0/1)
                float* __restrict__ C,
                int ldc)
{
    __shared__ float As[BK][BM];
    __shared__ float Bs[BK][BN + 1];
    __shared__ float red[BM][17];

    const int tid = threadIdx.x;
    const int tx = tid & 15;
    const int ty = tid >> 4;
    const int m0 = blockIdx.x * BM;
    const int n0 = blockIdx.y * BN;

    float acc[TM][TN];
#pragma unroll
    for (int i = 0; i < TM; i++)
#pragma unroll
        for (int j = 0; j < TN; j++) acc[i][j] = 0.f;

    for (int k0 = 0; k0 < K; k0 += BK) {
        // ---- load A tile (BM x BK), store transposed As[k][m] ----
#pragma unroll
        for (int t = tid; t < BM * BK; t += NTHREADS) {
            int mi = t >> 4, ki = t & 15;
            int kk = k0 + ki;
            int m  = m0 + mi;
            float v = 0.f;
            if (MODE == 0) {
                if (kk < 256)      v = A[m * 256 + kk];
                else if (kk < 288) v = p0[m * UDIM + (kk - 256)];
                else if (kk == 288) v = p1[m];
            } else {
                if (kk < K) v = A[m * K + kk];
            }
            As[ki][mi] = v;
        }
        // ---- load W tile (BN x BK), store transposed Bs[k][n] ----
#pragma unroll
        for (int t = tid; t < BN * BK; t += NTHREADS) {
            int ni = t >> 4, ki = t & 15;
            int kk = k0 + ki;
            int n  = n0 + ni;
            float v = 0.f;
            if (kk < K && n < N) v = W[n * K + kk];
            Bs[ki][ni] = v;
        }
        __syncthreads();
#pragma unroll
        for (int kk = 0; kk < BK; kk++) {
            float a[TM], b[TN];
#pragma unroll
            for (int i = 0; i < TM; i++) a[i] = As[kk][ty * TM + i];
#pragma unroll
            for (int j = 0; j < TN; j++) b[j] = Bs[kk][tx * TN + j];
#pragma unroll
            for (int i = 0; i < TM; i++)
#pragma unroll
                for (int j = 0; j < TN; j++) acc[i][j] += a[i] * b[j];
        }
        __syncthreads();
    }

    // ---------------- epilogues ----------------
    if (MODE <= 1) {
        const float inv_s = rsqrtf(1.0f + 1e-5f);
#pragma unroll
        for (int j = 0; j < TN; j++) {
            int n = n0 + tx * TN + j;
            float bi = bias[n];
            float gg = p2[n] * inv_s;
            float bb = p3[n];
#pragma unroll
            for (int i = 0; i < TM; i++) {
                int m = m0 + ty * TM + i;
                float v = (acc[i][j] + bi) * gg + bb;
                C[m * ldc + n] = fmaxf(v, 0.f);
            }
        }
    } else if (MODE == 2) {
#pragma unroll
        for (int j = 0; j < TN; j++) {
            int n = n0 + tx * TN + j;
            float bi = bias[n];
#pragma unroll
            for (int i = 0; i < TM; i++) {
                int m = m0 + ty * TM + i;
                C[m * ldc + n] = acc[i][j] + bi;
            }
        }
    } else if (MODE == 3 || MODE == 5) {
        // contract groups of 32 columns with ut*dt; this thread's 8 cols all
        // lie in group g = tx/4; u index of col j is (n & 31)
        float bi[TN];
        int   uu[TN];
#pragma unroll
        for (int j = 0; j < TN; j++) {
            int n = n0 + tx * TN + j;
            bi[j] = (n < N) ? bias[n] : 0.f;   // invalid cols: acc==0 && bi==0 -> 0
            uu[j] = n & 31;
        }
        float part[TM];
#pragma unroll
        for (int i = 0; i < TM; i++) {
            int m = m0 + ty * TM + i;
            float dtv = p1[m];
            float s = 0.f;
#pragma unroll
            for (int j = 0; j < TN; j++)
                s += (acc[i][j] + bi[j]) * p0[m * UDIM + uu[j]];
            part[i] = s * dtv;
        }
#pragma unroll
        for (int i = 0; i < TM; i++) red[ty * TM + i][tx] = part[i];
        __syncthreads();
        // 128 rows x 4 groups = 512 outputs
        for (int t = tid; t < BM * 4; t += NTHREADS) {
            int row = t & 127;
            int gg  = t >> 7;
            float s = red[row][4 * gg] + red[row][4 * gg + 1] +
                      red[row][4 * gg + 2] + red[row][4 * gg + 3];
            int ncol = n0 + gg * 32;
            if (ncol < N) {
                int m = m0 + row;
                C[m * ldc + (ncol >> 5)] = s;
            }
        }
    } else {  // MODE 4: contract all 128 cols with zv[m, c]
        float bi[TN];
#pragma unroll
        for (int j = 0; j < TN; j++) bi[j] = bias[n0 + tx * TN + j];
        float part[TM];
#pragma unroll
        for (int i = 0; i < TM; i++) {
            int m = m0 + ty * TM + i;
            float s = 0.f;
#pragma unroll
            for (int j = 0; j < TN; j++) {
                int cl = tx * TN + j;
                s += (acc[i][j] + bi[j]) * p0[m * 256 + cl];
            }
            part[i] = s;
        }
#pragma unroll
        for (int i = 0; i < TM; i++) red[ty * TM + i][tx] = part[i];
        __syncthreads();
        for (int t = tid; t < BM; t += NTHREADS) {
            float s = 0.f;
#pragma unroll
            for (int x = 0; x < 16; x++) s += red[t][x];
            int m = m0 + t;
            C[m * ldc + blockIdx.y] = s;
        }
    }
}

// z_next = exp(-softplus(a) + i*omega) * z + zincr ;  exp(-softplus(a)) = 1/(1+e^a)
__global__ void znext_kernel(const float* __restrict__ zt, float* __restrict__ out)
{
    int idx = blockIdx.x * blockDim.x + threadIdx.x;
    if (idx >= BATCH * CD) return;
    int m = idx >> 7, c = idx & 127;
    float a = g_ao[m * 256 + c];
    float w = g_ao[m * 256 + 128 + c];
    float ea = 1.f / (1.f + expf(a));
    float lr = ea * cosf(w);
    float li = ea * sinf(w);
    float zr = zt[m * 256 + c];
    float zi = zt[m * 256 + 128 + c];
    float znr = lr * zr - li * zi + g_zincr_r[idx];
    float zni = lr * zi + li * zr + g_zincr_i[idx];
    out[m * 256 + c]       = znr;
    out[m * 256 + 128 + c] = zni;
}

__global__ void yt_combine_kernel(float* __restrict__ out)
{
    int idx = blockIdx.x * blockDim.x + threadIdx.x;
    if (idx >= BATCH * NY) return;
    out[BATCH * LATENT + idx] = g_ytr[idx] - g_yti[idx] + g_ytd[idx];
}

extern "C" void kernel_launch(void* const* d_in, const int* in_sizes, int n_in,
                              void* d_out, int out_size)
{
    const float* zt      = (const float*)d_in[0];
    const float* dt      = (const float*)d_in[1];
    const float* ut      = (const float*)d_in[2];
    const float* sel_w0  = (const float*)d_in[3];
    const float* sel_b0  = (const float*)d_in[4];
    const float* sel_g0  = (const float*)d_in[5];
    const float* sel_be0 = (const float*)d_in[6];
    const float* sel_w1  = (const float*)d_in[7];
    const float* sel_b1  = (const float*)d_in[8];
    const float* sel_g1  = (const float*)d_in[9];
    const float* sel_be1 = (const float*)d_in[10];
    const float* sel_w2  = (const float*)d_in[11];
    const float* sel_b2  = (const float*)d_in[12];
    const float* alpha_w = (const float*)d_in[13];
    const float* alpha_b = (const float*)d_in[14];
    const float* omega_w = (const float*)d_in[15];
    const float* omega_b = (const float*)d_in[16];
    const float* btr_w   = (const float*)d_in[17];
    const float* btr_b   = (const float*)d_in[18];
    const float* bti_w   = (const float*)d_in[19];
    const float* bti_b   = (const float*)d_in[20];
    const float* ctr_w   = (const float*)d_in[21];
    const float* ctr_b   = (const float*)d_in[22];
    const float* cti_w   = (const float*)d_in[23];
    const float* cti_b   = (const float*)d_in[24];
    const float* dtw_w   = (const float*)d_in[25];
    const float* dtw_b   = (const float*)d_in[26];
    float* out = (float*)d_out;

    float *x1, *x2, *hz, *ao, *zir, *zii, *ytr, *yti, *ytd;
    cudaGetSymbolAddress((void**)&x1,  g_x1);
    cudaGetSymbolAddress((void**)&x2,  g_x2);
    cudaGetSymbolAddress((void**)&hz,  g_hz);
    cudaGetSymbolAddress((void**)&ao,  g_ao);
    cudaGetSymbolAddress((void**)&zir, g_zincr_r);
    cudaGetSymbolAddress((void**)&zii, g_zincr_i);
    cudaGetSymbolAddress((void**)&ytr, g_ytr);
    cudaGetSymbolAddress((void**)&yti, g_yti);
    cudaGetSymbolAddress((void**)&ytd, g_ytd);

    dim3 thr(NTHREADS);

    // selector MLP
    gemm_fused<0><<<dim3(64, 2), thr>>>(zt, 289, sel_w0, 256, sel_b0,
                                        ut, dt, sel_g0, sel_be0, x1, 256);
    gemm_fused<1><<<dim3(64, 2), thr>>>(x1, 256, sel_w1, 256, sel_b1,
                                        nullptr, nullptr, sel_g1, sel_be1, x2, 256);
    gemm_fused<2><<<dim3(64, 2), thr>>>(x2, 256, sel_w2, 256, sel_b2,
                                        nullptr, nullptr, nullptr, nullptr, hz, 256);
    // alpha | omega into g_ao
    gemm_fused<2><<<dim3(64, 1), thr>>>(hz, 256, alpha_w, 128, alpha_b,
                                        nullptr, nullptr, nullptr, nullptr, ao, 256);
    gemm_fused<2><<<dim3(64, 1), thr>>>(hz, 256, omega_w, 128, omega_b,
                                        nullptr, nullptr, nullptr, nullptr, ao + 128, 256);
    // Bt (real, imag) fused with einsum('bcu,bu->bc')
    gemm_fused<3><<<dim3(64, 32), thr>>>(hz, 256, btr_w, 4096, btr_b,
                                         ut, dt, nullptr, nullptr, zir, CD);
    gemm_fused<3><<<dim3(64, 32), thr>>>(hz, 256, bti_w, 4096, bti_b,
                                         ut, dt, nullptr, nullptr, zii, CD);
    // z_next into d_out[:, 0:256]
    znext_kernel<<<(BATCH * CD) / 256, 256>>>(zt, out);
    // Ct (real, imag) fused with einsum('byc,bc->by'); reads z_next from d_out
    gemm_fused<4><<<dim3(64, 50), thr>>>(hz, 256, ctr_w, 6400, ctr_b,
                                         out, nullptr, nullptr, nullptr, ytr, NY);
    gemm_fused<4><<<dim3(64, 50), thr>>>(hz, 256, cti_w, 6400, cti_b,
                                         out + 128, nullptr, nullptr, nullptr, yti, NY);
    // Dt fused with einsum('byu,bu->by')
    gemm_fused<5><<<dim3(64, 13), thr>>>(hz, 256, dtw_w, 1600, dtw_b,
                                         ut, dt, nullptr, nullptr, ytd, NY);
    // yt = Re(Ct z) + Dt utdt
    yt_combine_kernel<<<(BATCH * NY + 255) / 256, 256>>>(out);
}

// round 2
// speedup vs baseline: 4.0114x; 4.0114x over previous
#include <cuda_runtime.h>
#include <math.h>
#include <stdint.h>

#define BATCH  8192
#define LATENT 256
#define CD     128
#define UDIM   32
#define NY     50

#define NTHREADS 256

// ---------------- scratch (static device globals; no allocation) ----------------
__device__ float g_x1[BATCH * LATENT];
__device__ float g_x2[BATCH * LATENT];
__device__ float g_hz[BATCH * LATENT];
__device__ float g_ao[BATCH * LATENT];      // [:,0:128]=alpha pre-act, [:,128:256]=omega
__device__ float g_zincr_r[BATCH * CD];
__device__ float g_zincr_i[BATCH * CD];
__device__ float g_ytr[BATCH * NY];
__device__ float g_yti[BATCH * NY];
__device__ float g_ytd[BATCH * NY];

// ---------------- small PTX helpers ----------------
__device__ __forceinline__ uint32_t f2tf32(float f) {
    uint32_t r;
    asm("cvt.rna.tf32.f32 %0, %1;" : "=r"(r) : "f"(f));
    return r;
}

__device__ __forceinline__ void ldsm4(uint32_t& a0, uint32_t& a1, uint32_t& a2, uint32_t& a3,
                                      uint32_t addr) {
    asm volatile("ldmatrix.sync.aligned.m8n8.x4.shared.b16 {%0,%1,%2,%3}, [%4];"
                 : "=r"(a0), "=r"(a1), "=r"(a2), "=r"(a3) : "r"(addr));
}

__device__ __forceinline__ void mma_tf32(float* c,
                                         uint32_t a0, uint32_t a1, uint32_t a2, uint32_t a3,
                                         uint32_t b0, uint32_t b1) {
    asm volatile(
        "mma.sync.aligned.m16n8k8.row.col.f32.tf32.tf32.f32 "
        "{%0,%1,%2,%3},{%4,%5,%6,%7},{%8,%9},{%0,%1,%2,%3};"
        : "+f"(c[0]), "+f"(c[1]), "+f"(c[2]), "+f"(c[3])
        : "r"(a0), "r"(a1), "r"(a2), "r"(a3), "r"(b0), "r"(b1));
}

// ---------------------------------------------------------------------------
// Tensor-core fused GEMM: C = A[M,K] @ W[N,K]^T (+bias), epilogue per MODE:
//   MODE 0: A = concat(zt, ut, dt) (K=289), epilogue BN(eval)+ReLU
//   MODE 1: plain A, epilogue BN(eval)+ReLU
//   MODE 2: plain A, epilogue +bias, store
//   MODE 3: +bias then contract 32-col u-groups with ut*dt  (Bt)
//   MODE 4: +bias then contract 128 cols with z_next part   (Ct)
//   MODE 5: like MODE 3 with bounds checks (Dt, N=1600)
// CTA tile 128x128, BK=32, 8 warps as 2(m) x 4(n), warp tile 64x32.
// ---------------------------------------------------------------------------
template <int MODE>
__global__ __launch_bounds__(NTHREADS)
void gemm_tc(const float* __restrict__ A, int K,
             const float* __restrict__ W, int N,
             const float* __restrict__ bias,
             const float* __restrict__ p0,   // ut (0/3/5) | zv base (4)
             const float* __restrict__ p1,   // dt (0/3/5)
             const float* __restrict__ p2,   // bn gamma (0/1)
             const float* __restrict__ p3,   // bn beta  (0/1)
             float* __restrict__ C, int ldc)
{
    __shared__ uint32_t As[128 * 36];   // tf32 bits, row m, stride 36 (conflict-free)
    __shared__ uint32_t Bs[128 * 36];   // tf32 bits, row n, stride 36
    __shared__ float red[128 * 4];      // MODE 4 cross-warp reduce

    const int tid  = threadIdx.x;
    const int lane = tid & 31;
    const int warp = tid >> 5;
    const int m0 = blockIdx.x * 128;
    const int n0 = blockIdx.y * 128;
    const int mwarp = (warp >> 2) * 64;
    const int nwarp = (warp & 3) * 32;
    const int gq = lane >> 2;           // mma group id
    const int tq = lane & 3;            // thread-in-group

    float acc[4][4][4];
#pragma unroll
    for (int i = 0; i < 4; i++)
#pragma unroll
        for (int j = 0; j < 4; j++)
#pragma unroll
            for (int r = 0; r < 4; r++) acc[i][j][r] = 0.f;

    // ldmatrix per-thread row addresses (threads 0-7: m+0..7; 8-15: m+8..15;
    // 16-23: m+0..7 cols +4; 24-31: m+8..15 cols +4)
    const uint32_t as_u = (uint32_t)__cvta_generic_to_shared(As);
    const int row_off = (lane & 7) + ((lane & 8) ? 8 : 0);
    const int col_off = (lane & 16) ? 4 : 0;
    uint32_t a_addr[4];
#pragma unroll
    for (int mt = 0; mt < 4; mt++)
        a_addr[mt] = as_u + (uint32_t)(((mwarp + mt * 16 + row_off) * 36 + col_off) * 4);

    int b_idx[4];
#pragma unroll
    for (int nt = 0; nt < 4; nt++)
        b_idx[nt] = (nwarp + nt * 8 + gq) * 36 + tq;

    auto compute = [&]() {
#pragma unroll
        for (int ks = 0; ks < 4; ks++) {
            const int kk = ks * 8;
            uint32_t bf0[4], bf1[4];
#pragma unroll
            for (int nt = 0; nt < 4; nt++) {
                bf0[nt] = Bs[b_idx[nt] + kk];
                bf1[nt] = Bs[b_idx[nt] + kk + 4];
            }
#pragma unroll
            for (int mt = 0; mt < 4; mt++) {
                uint32_t a0, a1, a2, a3;
                ldsm4(a0, a1, a2, a3, a_addr[mt] + (uint32_t)(kk * 4));
#pragma unroll
                for (int nt = 0; nt < 4; nt++)
                    mma_tf32(acc[mt][nt], a0, a1, a2, a3, bf0[nt], bf1[nt]);
            }
        }
    };

    if (MODE == 0) {
        // K=289 concat path, simple (tiny fraction of total work)
        const int NC = (K + 31) / 32;
        for (int kc = 0; kc < NC; kc++) {
#pragma unroll
            for (int i = 0; i < 16; i++) {
                int l = tid + i * 256;
                int r = l >> 5, c = l & 31;
                int kk = kc * 32 + c;
                int m = m0 + r;
                float v = 0.f;
                if (kk < 256)      v = A[m * 256 + kk];
                else if (kk < 288) v = p0[m * UDIM + (kk - 256)];
                else if (kk == 288) v = p1[m];
                As[r * 36 + c] = f2tf32(v);
                int n = n0 + r;
                float wv = 0.f;
                if (kk < K && n < N) wv = W[n * K + kk];
                Bs[r * 36 + c] = f2tf32(wv);
            }
            __syncthreads();
            compute();
            __syncthreads();
        }
    } else {
        // dense path, K % 32 == 0, register-prefetch pipeline
        const int NC = K >> 5;
        float4 av[4], bv[4];
        auto gload = [&](int kc) {
#pragma unroll
            for (int i = 0; i < 4; i++) {
                int l = tid + i * 256;
                int r = l >> 3, c = l & 7;
                av[i] = *reinterpret_cast<const float4*>(&A[(m0 + r) * K + kc * 32 + c * 4]);
                int n = n0 + r;
                bv[i] = (n < N)
                        ? *reinterpret_cast<const float4*>(&W[n * K + kc * 32 + c * 4])
                        : make_float4(0.f, 0.f, 0.f, 0.f);
            }
        };
        auto sstore = [&]() {
#pragma unroll
            for (int i = 0; i < 4; i++) {
                int l = tid + i * 256;
                int r = l >> 3, c = l & 7;
                uint32_t* pa = &As[r * 36 + c * 4];
                pa[0] = f2tf32(av[i].x); pa[1] = f2tf32(av[i].y);
                pa[2] = f2tf32(av[i].z); pa[3] = f2tf32(av[i].w);
                uint32_t* pb = &Bs[r * 36 + c * 4];
                pb[0] = f2tf32(bv[i].x); pb[1] = f2tf32(bv[i].y);
                pb[2] = f2tf32(bv[i].z); pb[3] = f2tf32(bv[i].w);
            }
        };
        gload(0);
        sstore();
        __syncthreads();
        for (int kc = 0; kc < NC; kc++) {
            bool more = (kc + 1) < NC;
            if (more) gload(kc + 1);
            compute();
            __syncthreads();
            if (more) { sstore(); __syncthreads(); }
        }
    }

    // ---------------- epilogues ----------------
    // accumulator r = h*2+p maps to: m = m0+mwarp+mt*16+gq+h*8 ; n = n0+nwarp+nt*8+tq*2+p
    if (MODE <= 1) {
        const float inv_s = rsqrtf(1.0f + 1e-5f);
#pragma unroll
        for (int nt = 0; nt < 4; nt++)
#pragma unroll
            for (int p = 0; p < 2; p++) {
                int n = n0 + nwarp + nt * 8 + tq * 2 + p;
                float bi = bias[n];
                float gg = p2[n] * inv_s;
                float bb = p3[n];
#pragma unroll
                for (int mt = 0; mt < 4; mt++)
#pragma unroll
                    for (int h = 0; h < 2; h++) {
                        int m = m0 + mwarp + mt * 16 + gq + h * 8;
                        float v = (acc[mt][nt][h * 2 + p] + bi) * gg + bb;
                        C[m * ldc + n] = fmaxf(v, 0.f);
                    }
            }
    } else if (MODE == 2) {
#pragma unroll
        for (int nt = 0; nt < 4; nt++)
#pragma unroll
            for (int p = 0; p < 2; p++) {
                int n = n0 + nwarp + nt * 8 + tq * 2 + p;
                if (n >= N) continue;
                float bi = bias[n];
#pragma unroll
                for (int mt = 0; mt < 4; mt++)
#pragma unroll
                    for (int h = 0; h < 2; h++) {
                        int m = m0 + mwarp + mt * 16 + gq + h * 8;
                        C[m * ldc + n] = acc[mt][nt][h * 2 + p] + bi;
                    }
            }
    } else if (MODE == 3 || MODE == 5) {
        // warp's 32 n-columns == one u-group; contraction completes in-warp
        const int gcol = blockIdx.y * 4 + (warp & 3);
        const bool gvalid = (MODE == 3) || (gcol * 32 < N);
#pragma unroll
        for (int mt = 0; mt < 4; mt++)
#pragma unroll
            for (int h = 0; h < 2; h++) {
                int m = m0 + mwarp + mt * 16 + gq + h * 8;
                float s = 0.f;
#pragma unroll
                for (int nt = 0; nt < 4; nt++)
#pragma unroll
                    for (int p = 0; p < 2; p++) {
                        int u = nt * 8 + tq * 2 + p;
                        int n = n0 + nwarp + u;
                        float bi = (MODE == 3) ? bias[n] : ((n < N) ? bias[n] : 0.f);
                        s += (acc[mt][nt][h * 2 + p] + bi) * p0[m * UDIM + u];
                    }
                s += __shfl_xor_sync(0xffffffffu, s, 1);
                s += __shfl_xor_sync(0xffffffffu, s, 2);
                if (tq == 0 && gvalid)
                    C[m * ldc + gcol] = s * p1[m];
            }
    } else {  // MODE 4: contract all 128 block-columns with zv[m, c]
#pragma unroll
        for (int mt = 0; mt < 4; mt++)
#pragma unroll
            for (int h = 0; h < 2; h++) {
                int m = m0 + mwarp + mt * 16 + gq + h * 8;
                float s = 0.f;
#pragma unroll
                for (int nt = 0; nt < 4; nt++)
#pragma unroll
                    for (int p = 0; p < 2; p++) {
                        int cl = nwarp + nt * 8 + tq * 2 + p;
                        s += (acc[mt][nt][h * 2 + p] + bias[n0 + cl]) * p0[m * 256 + cl];
                    }
                s += __shfl_xor_sync(0xffffffffu, s, 1);
                s += __shfl_xor_sync(0xffffffffu, s, 2);
                if (tq == 0)
                    red[(mwarp + mt * 16 + gq + h * 8) * 4 + (warp & 3)] = s;
            }
        __syncthreads();
        if (tid < 128) {
            float s = red[tid * 4] + red[tid * 4 + 1] + red[tid * 4 + 2] + red[tid * 4 + 3];
            C[(m0 + tid) * ldc + blockIdx.y] = s;
        }
    }
}

// z_next = exp(-softplus(a) + i*omega) * z + zincr ;  exp(-softplus(a)) = 1/(1+e^a)
__global__ void znext_kernel(const float* __restrict__ zt, float* __restrict__ out)
{
    int idx = blockIdx.x * blockDim.x + threadIdx.x;
    if (idx >= BATCH * CD) return;
    int m = idx >> 7, c = idx & 127;
    float a = g_ao[m * 256 + c];
    float w = g_ao[m * 256 + 128 + c];
    float ea = 1.f / (1.f + expf(a));
    float lr = ea * cosf(w);
    float li = ea * sinf(w);
    float zr = zt[m * 256 + c];
    float zi = zt[m * 256 + 128 + c];
    float znr = lr * zr - li * zi + g_zincr_r[idx];
    float zni = lr * zi + li * zr + g_zincr_i[idx];
    out[m * 256 + c]       = znr;
    out[m * 256 + 128 + c] = zni;
}

__global__ void yt_combine_kernel(float* __restrict__ out)
{
    int idx = blockIdx.x * blockDim.x + threadIdx.x;
    if (idx >= BATCH * NY) return;
    out[BATCH * LATENT + idx] = g_ytr[idx] - g_yti[idx] + g_ytd[idx];
}

extern "C" void kernel_launch(void* const* d_in, const int* in_sizes, int n_in,
                              void* d_out, int out_size)
{
    const float* zt      = (const float*)d_in[0];
    const float* dt      = (const float*)d_in[1];
    const float* ut      = (const float*)d_in[2];
    const float* sel_w0  = (const float*)d_in[3];
    const float* sel_b0  = (const float*)d_in[4];
    const float* sel_g0  = (const float*)d_in[5];
    const float* sel_be0 = (const float*)d_in[6];
    const float* sel_w1  = (const float*)d_in[7];
    const float* sel_b1  = (const float*)d_in[8];
    const float* sel_g1  = (const float*)d_in[9];
    const float* sel_be1 = (const float*)d_in[10];
    const float* sel_w2  = (const float*)d_in[11];
    const float* sel_b2  = (const float*)d_in[12];
    const float* alpha_w = (const float*)d_in[13];
    const float* alpha_b = (const float*)d_in[14];
    const float* omega_w = (const float*)d_in[15];
    const float* omega_b = (const float*)d_in[16];
    const float* btr_w   = (const float*)d_in[17];
    const float* btr_b   = (const float*)d_in[18];
    const float* bti_w   = (const float*)d_in[19];
    const float* bti_b   = (const float*)d_in[20];
    const float* ctr_w   = (const float*)d_in[21];
    const float* ctr_b   = (const float*)d_in[22];
    const float* cti_w   = (const float*)d_in[23];
    const float* cti_b   = (const float*)d_in[24];
    const float* dtw_w   = (const float*)d_in[25];
    const float* dtw_b   = (const float*)d_in[26];
    float* out = (float*)d_out;

    float *x1, *x2, *hz, *ao, *zir, *zii, *ytr, *yti, *ytd;
    cudaGetSymbolAddress((void**)&x1,  g_x1);
    cudaGetSymbolAddress((void**)&x2,  g_x2);
    cudaGetSymbolAddress((void**)&hz,  g_hz);
    cudaGetSymbolAddress((void**)&ao,  g_ao);
    cudaGetSymbolAddress((void**)&zir, g_zincr_r);
    cudaGetSymbolAddress((void**)&zii, g_zincr_i);
    cudaGetSymbolAddress((void**)&ytr, g_ytr);
    cudaGetSymbolAddress((void**)&yti, g_yti);
    cudaGetSymbolAddress((void**)&ytd, g_ytd);

    dim3 thr(NTHREADS);

    // selector MLP
    gemm_tc<0><<<dim3(64, 2), thr>>>(zt, 289, sel_w0, 256, sel_b0,
                                     ut, dt, sel_g0, sel_be0, x1, 256);
    gemm_tc<1><<<dim3(64, 2), thr>>>(x1, 256, sel_w1, 256, sel_b1,
                                     nullptr, nullptr, sel_g1, sel_be1, x2, 256);
    gemm_tc<2><<<dim3(64, 2), thr>>>(x2, 256, sel_w2, 256, sel_b2,
                                     nullptr, nullptr, nullptr, nullptr, hz, 256);
    // alpha | omega into g_ao
    gemm_tc<2><<<dim3(64, 1), thr>>>(hz, 256, alpha_w, 128, alpha_b,
                                     nullptr, nullptr, nullptr, nullptr, ao, 256);
    gemm_tc<2><<<dim3(64, 1), thr>>>(hz, 256, omega_w, 128, omega_b,
                                     nullptr, nullptr, nullptr, nullptr, ao + 128, 256);
    // Bt (real, imag) fused with einsum('bcu,bu->bc')
    gemm_tc<3><<<dim3(64, 32), thr>>>(hz, 256, btr_w, 4096, btr_b,
                                      ut, dt, nullptr, nullptr, zir, CD);
    gemm_tc<3><<<dim3(64, 32), thr>>>(hz, 256, bti_w, 4096, bti_b,
                                      ut, dt, nullptr, nullptr, zii, CD);
    // z_next into d_out[:, 0:256]
    znext_kernel<<<(BATCH * CD) / 256, 256>>>(zt, out);
    // Ct (real, imag) fused with einsum('byc,bc->by'); reads z_next from d_out
    gemm_tc<4><<<dim3(64, 50), thr>>>(hz, 256, ctr_w, 6400, ctr_b,
                                      out, nullptr, nullptr, nullptr, ytr, NY);
    gemm_tc<4><<<dim3(64, 50), thr>>>(hz, 256, cti_w, 6400, cti_b,
                                      out + 128, nullptr, nullptr, nullptr, yti, NY);
    // Dt fused with einsum('byu,bu->by')
    gemm_tc<5><<<dim3(64, 13), thr>>>(hz, 256, dtw_w, 1600, dtw_b,
                                      ut, dt, nullptr, nullptr, ytd, NY);
    // yt = Re(Ct z) + Dt utdt
    yt_combine_kernel<<<(BATCH * NY + 255) / 256, 256>>>(out);
}

// round 3
// speedup vs baseline: 4.7783x; 1.1912x over previous
#include <cuda_runtime.h>
#include <math.h>
#include <stdint.h>

#define BATCH  8192
#define LATENT 256
#define CD     128
#define UDIM   32
#define NY     50
#define NTHREADS 256
#define STAGES 4
// dynamic smem: STAGES stages of (128x32 A + 128x32 B) floats, + 512 reduce floats
#define SMEM_FLOATS (STAGES * 8192 + 512)
#define SMEM_BYTES  (SMEM_FLOATS * 4)

// ---------------- scratch (static device globals; no allocation) ----------------
// pre-rounded (tf32-rna) GEMM operands
__device__ float g_A0 [BATCH * 320];    // concat(zt,ut,dt) zero-padded K=320
__device__ float g_W0 [256 * 320];      // sel_w0 padded 289->320
__device__ float g_W1 [256 * 256];
__device__ float g_W2 [256 * 256];
__device__ float g_Wao[256 * 256];      // rows 0-127 alpha_w, 128-255 omega_w
__device__ float g_Bao[256];            // concat bias (fp32, unrounded)
__device__ float g_Wbtr[4096 * 256];
__device__ float g_Wbti[4096 * 256];
__device__ float g_Wctr[6400 * 256];
__device__ float g_Wcti[6400 * 256];
__device__ float g_Wdtw[1600 * 256];
// activations / partials
__device__ float g_x1[BATCH * LATENT];
__device__ float g_x2[BATCH * LATENT];
__device__ float g_hz[BATCH * LATENT];
__device__ float g_ao[BATCH * LATENT];
__device__ float g_zincr_r[BATCH * CD];
__device__ float g_zincr_i[BATCH * CD];
__device__ float g_ytr[BATCH * NY];
__device__ float g_yti[BATCH * NY];
__device__ float g_ytd[BATCH * NY];

// ---------------- small PTX helpers ----------------
__device__ __forceinline__ uint32_t f2tf32(float f) {
    uint32_t r;
    asm("cvt.rna.tf32.f32 %0, %1;" : "=r"(r) : "f"(f));
    return r;
}
__device__ __forceinline__ float rnd_tf32(float f) { return __uint_as_float(f2tf32(f)); }

__device__ __forceinline__ void ldsm4(uint32_t& a0, uint32_t& a1, uint32_t& a2, uint32_t& a3,
                                      uint32_t addr) {
    asm volatile("ldmatrix.sync.aligned.m8n8.x4.shared.b16 {%0,%1,%2,%3}, [%4];"
                 : "=r"(a0), "=r"(a1), "=r"(a2), "=r"(a3) : "r"(addr));
}
__device__ __forceinline__ void mma_tf32(float* c,
                                         uint32_t a0, uint32_t a1, uint32_t a2, uint32_t a3,
                                         uint32_t b0, uint32_t b1) {
    asm volatile(
        "mma.sync.aligned.m16n8k8.row.col.f32.tf32.tf32.f32 "
        "{%0,%1,%2,%3},{%4,%5,%6,%7},{%8,%9},{%0,%1,%2,%3};"
        : "+f"(c[0]), "+f"(c[1]), "+f"(c[2]), "+f"(c[3])
        : "r"(a0), "r"(a1), "r"(a2), "r"(a3), "r"(b0), "r"(b1));
}
__device__ __forceinline__ void cp16(uint32_t dst, const float* src, int sz) {
    asm volatile("cp.async.cg.shared.global [%0], [%1], 16, %2;"
                 :: "r"(dst), "l"(src), "r"(sz));
}

// ---------------------------------------------------------------------------
// prep: round all GEMM operands to tf32 (rna) into scratch; build concat A0/W0/Wao
// ---------------------------------------------------------------------------
#define S_A0  0
#define E_A0  (BATCH * 320)                 // 2,621,440
#define E_W0  (E_A0  + 256 * 320)           // 2,703,360
#define E_W1  (E_W0  + 65536)               // 2,768,896
#define E_W2  (E_W1  + 65536)               // 2,834,432
#define E_WAO (E_W2  + 65536)               // 2,899,968
#define E_BAO (E_WAO + 256)                 // 2,900,224
#define E_BTR (E_BAO + 4096 * 256)          // 3,948,800
#define E_BTI (E_BTR + 4096 * 256)          // 4,997,376
#define E_CTR (E_BTI + 6400 * 256)          // 6,635,776
#define E_CTI (E_CTR + 6400 * 256)          // 8,274,176
#define E_DTW (E_CTI + 1600 * 256)          // 8,683,776
#define PREP_TOTAL E_DTW

__global__ void prep_kernel(const float* __restrict__ zt, const float* __restrict__ dt,
                            const float* __restrict__ ut,
                            const float* __restrict__ sw0, const float* __restrict__ sw1,
                            const float* __restrict__ sw2,
                            const float* __restrict__ aw, const float* __restrict__ ab,
                            const float* __restrict__ ow, const float* __restrict__ ob,
                            const float* __restrict__ btr, const float* __restrict__ bti,
                            const float* __restrict__ ctr, const float* __restrict__ cti,
                            const float* __restrict__ dtw)
{
    for (int idx = blockIdx.x * blockDim.x + threadIdx.x; idx < PREP_TOTAL;
         idx += gridDim.x * blockDim.x) {
        if (idx < E_A0) {
            int m = idx / 320, c = idx % 320;
            float v = 0.f;
            if (c < 256)      v = zt[m * 256 + c];
            else if (c < 288) v = ut[m * UDIM + (c - 256)];
            else if (c == 288) v = dt[m];
            g_A0[idx] = rnd_tf32(v);
        } else if (idx < E_W0) {
            int j = idx - E_A0;
            int r = j / 320, c = j % 320;
            g_W0[j] = (c < 289) ? rnd_tf32(sw0[r * 289 + c]) : 0.f;
        } else if (idx < E_W1) {
            int j = idx - E_W0;  g_W1[j] = rnd_tf32(sw1[j]);
        } else if (idx < E_W2) {
            int j = idx - E_W1;  g_W2[j] = rnd_tf32(sw2[j]);
        } else if (idx < E_WAO) {
            int j = idx - E_W2;
            g_Wao[j] = rnd_tf32((j < 128 * 256) ? aw[j] : ow[j - 128 * 256]);
        } else if (idx < E_BAO) {
            int j = idx - E_WAO;
            g_Bao[j] = (j < 128) ? ab[j] : ob[j - 128];
        } else if (idx < E_BTR) {
            int j = idx - E_BAO; g_Wbtr[j] = rnd_tf32(btr[j]);
        } else if (idx < E_BTI) {
            int j = idx - E_BTR; g_Wbti[j] = rnd_tf32(bti[j]);
        } else if (idx < E_CTR) {
            int j = idx - E_BTI; g_Wctr[j] = rnd_tf32(ctr[j]);
        } else if (idx < E_CTI) {
            int j = idx - E_CTR; g_Wcti[j] = rnd_tf32(cti[j]);
        } else {
            int j = idx - E_CTI; g_Wdtw[j] = rnd_tf32(dtw[j]);
        }
    }
}

// ---------------------------------------------------------------------------
// Tensor-core fused GEMM: C = A[M,K] @ W[N,K]^T (+bias), epilogue per MODE:
//   MODE 1: BN(eval)+ReLU              (ROUND: tf32-round the store)
//   MODE 2: +bias, store               (ROUND optional)
//   MODE 3: +bias then contract 32-col u-groups with ut*dt  (Bt)
//   MODE 4: +bias then contract 128 cols with z_next part   (Ct)
//   MODE 5: like MODE 3 with N bounds checks (Dt)
// CTA 128x128, BK=32, 4-stage cp.async pipeline, XOR-swizzled smem.
// 8 warps as 2(m) x 4(n), warp tile 64x32. Inputs must be pre-rounded tf32.
// ---------------------------------------------------------------------------
template <int MODE, int ROUND>
__global__ __launch_bounds__(NTHREADS)
void gemm_tc(const float* __restrict__ A, int K,
             const float* __restrict__ W, int N,
             const float* __restrict__ bias,
             const float* __restrict__ p0,   // ut (3/5) | zv base (4)
             const float* __restrict__ p1,   // dt (3/5)
             const float* __restrict__ p2,   // bn gamma (1)
             const float* __restrict__ p3,   // bn beta  (1)
             float* __restrict__ C, int ldc)
{
    extern __shared__ float sm[];
    const uint32_t* smb = (const uint32_t*)sm;
    float* red = sm + STAGES * 8192;

    const int tid  = threadIdx.x;
    const int lane = tid & 31;
    const int warp = tid >> 5;
    const int m0 = blockIdx.x * 128;
    const int n0 = blockIdx.y * 128;
    const int mwarp = (warp >> 2) * 64;
    const int nwarp = (warp & 3) * 32;
    const int gq = lane >> 2;
    const int tq = lane & 3;
    const uint32_t smu = (uint32_t)__cvta_generic_to_shared(sm);

    float acc[4][4][4];
#pragma unroll
    for (int i = 0; i < 4; i++)
#pragma unroll
        for (int j = 0; j < 4; j++)
#pragma unroll
            for (int r = 0; r < 4; r++) acc[i][j][r] = 0.f;

    // ldmatrix lane constants: lanes 0-15 -> rows m..m+15 (k4 lo), 16-31 -> same rows (k4 hi)
    const int row_off = lane & 15;
    const int hi = (lane >> 4) & 1;
    uint32_t abyte[4]; int arx[4];
#pragma unroll
    for (int mt = 0; mt < 4; mt++) {
        int r = mwarp + mt * 16 + row_off;
        abyte[mt] = smu + (uint32_t)(r * 128);
        arx[mt] = r & 7;
    }
    int bidx[4], bx[4];
#pragma unroll
    for (int nt = 0; nt < 4; nt++) {
        int n = nwarp + nt * 8 + gq;
        bidx[nt] = n * 32 + tq;
        bx[nt] = n & 7;
    }

    auto issue = [&](int kc, int s) {
#pragma unroll
        for (int i = 0; i < 8; i++) {
            int idx = tid + i * 256;                 // 0..2047
            int r  = (idx & 1023) >> 3;
            int k4 = idx & 7;
            int dstf = s * 8192 + ((idx < 1024) ? 0 : 4096)
                       + r * 32 + ((k4 ^ (r & 7)) << 2);
            uint32_t da = smu + (uint32_t)(dstf * 4);
            if (idx < 1024) {
                cp16(da, A + (size_t)(m0 + r) * K + kc * 32 + k4 * 4, 16);
            } else {
                int n = n0 + r;
                int sz = 16;
                if (n >= N) { n = 0; sz = 0; }
                cp16(da, W + (size_t)n * K + kc * 32 + k4 * 4, sz);
            }
        }
        asm volatile("cp.async.commit_group;" ::: "memory");
    };

    auto compute = [&](int s) {
        const uint32_t sa = (uint32_t)(s * 8192 * 4);
        const int sbf = s * 8192 + 4096;
#pragma unroll
        for (int ks = 0; ks < 4; ks++) {
            uint32_t bf0[4], bf1[4];
#pragma unroll
            for (int nt = 0; nt < 4; nt++) {
                bf0[nt] = smb[sbf + bidx[nt] + (((2 * ks)     ^ bx[nt]) << 2)];
                bf1[nt] = smb[sbf + bidx[nt] + (((2 * ks + 1) ^ bx[nt]) << 2)];
            }
            const int k4a = 2 * ks + hi;
#pragma unroll
            for (int mt = 0; mt < 4; mt++) {
                uint32_t a0, a1, a2, a3;
                ldsm4(a0, a1, a2, a3, abyte[mt] + sa + (uint32_t)(((k4a ^ arx[mt]) << 4)));
#pragma unroll
                for (int nt = 0; nt < 4; nt++)
                    mma_tf32(acc[mt][nt], a0, a1, a2, a3, bf0[nt], bf1[nt]);
            }
        }
    };

    const int NC = K >> 5;
    issue(0, 0); issue(1, 1); issue(2, 2);
    for (int kc = 0; kc < NC; kc++) {
        asm volatile("cp.async.wait_group 2;" ::: "memory");
        __syncthreads();
        int pf = kc + STAGES - 1;
        if (pf < NC) issue(pf, pf & (STAGES - 1));
        else asm volatile("cp.async.commit_group;" ::: "memory");
        compute(kc & (STAGES - 1));
        __syncthreads();
    }

    // ---------------- epilogues ----------------
    // acc r=h*2+p -> m = m0+mwarp+mt*16+gq+h*8 ; n = n0+nwarp+nt*8+tq*2+p
    if (MODE == 1) {
        const float inv_s = rsqrtf(1.0f + 1e-5f);
#pragma unroll
        for (int nt = 0; nt < 4; nt++)
#pragma unroll
            for (int p = 0; p < 2; p++) {
                int n = n0 + nwarp + nt * 8 + tq * 2 + p;
                float bi = bias[n];
                float gg = p2[n] * inv_s;
                float bb = p3[n];
#pragma unroll
                for (int mt = 0; mt < 4; mt++)
#pragma unroll
                    for (int h = 0; h < 2; h++) {
                        int m = m0 + mwarp + mt * 16 + gq + h * 8;
                        float v = fmaxf((acc[mt][nt][h * 2 + p] + bi) * gg + bb, 0.f);
                        C[m * ldc + n] = ROUND ? rnd_tf32(v) : v;
                    }
            }
    } else if (MODE == 2) {
#pragma unroll
        for (int nt = 0; nt < 4; nt++)
#pragma unroll
            for (int p = 0; p < 2; p++) {
                int n = n0 + nwarp + nt * 8 + tq * 2 + p;
                float bi = bias[n];
#pragma unroll
                for (int mt = 0; mt < 4; mt++)
#pragma unroll
                    for (int h = 0; h < 2; h++) {
                        int m = m0 + mwarp + mt * 16 + gq + h * 8;
                        float v = acc[mt][nt][h * 2 + p] + bi;
                        C[m * ldc + n] = ROUND ? rnd_tf32(v) : v;
                    }
            }
    } else if (MODE == 3 || MODE == 5) {
        // warp's 32 n-columns == one u-group; contraction completes in-warp
        const int gcol = blockIdx.y * 4 + (warp & 3);
        const bool gvalid = (MODE == 3) || (gcol * 32 < N);
#pragma unroll
        for (int mt = 0; mt < 4; mt++)
#pragma unroll
            for (int h = 0; h < 2; h++) {
                int m = m0 + mwarp + mt * 16 + gq + h * 8;
                float s = 0.f;
#pragma unroll
                for (int nt = 0; nt < 4; nt++)
#pragma unroll
                    for (int p = 0; p < 2; p++) {
                        int u = nt * 8 + tq * 2 + p;
                        int n = n0 + nwarp + u;
                        float bi = (MODE == 3) ? bias[n] : ((n < N) ? bias[n] : 0.f);
                        s += (acc[mt][nt][h * 2 + p] + bi) * p0[m * UDIM + u];
                    }
                s += __shfl_xor_sync(0xffffffffu, s, 1);
                s += __shfl_xor_sync(0xffffffffu, s, 2);
                if (tq == 0 && gvalid)
                    C[m * ldc + gcol] = s * p1[m];
            }
    } else {  // MODE 4: contract all 128 block-columns with zv[m, c]
#pragma unroll
        for (int mt = 0; mt < 4; mt++)
#pragma unroll
            for (int h = 0; h < 2; h++) {
                int m = m0 + mwarp + mt * 16 + gq + h * 8;
                float s = 0.f;
#pragma unroll
                for (int nt = 0; nt < 4; nt++)
#pragma unroll
                    for (int p = 0; p < 2; p++) {
                        int cl = nwarp + nt * 8 + tq * 2 + p;
                        s += (acc[mt][nt][h * 2 + p] + bias[n0 + cl]) * p0[m * 256 + cl];
                    }
                s += __shfl_xor_sync(0xffffffffu, s, 1);
                s += __shfl_xor_sync(0xffffffffu, s, 2);
                if (tq == 0)
                    red[(mwarp + mt * 16 + gq + h * 8) * 4 + (warp & 3)] = s;
            }
        __syncthreads();
        if (tid < 128) {
            float s = red[tid * 4] + red[tid * 4 + 1] + red[tid * 4 + 2] + red[tid * 4 + 3];
            C[(m0 + tid) * ldc + blockIdx.y] = s;
        }
    }
}

// z_next = exp(-softplus(a) + i*omega) * z + zincr ;  exp(-softplus(a)) = 1/(1+e^a)
__global__ void znext_kernel(const float* __restrict__ zt, float* __restrict__ out)
{
    int idx = blockIdx.x * blockDim.x + threadIdx.x;
    if (idx >= BATCH * CD) return;
    int m = idx >> 7, c = idx & 127;
    float a = g_ao[m * 256 + c];
    float w = g_ao[m * 256 + 128 + c];
    float ea = 1.f / (1.f + expf(a));
    float lr = ea * cosf(w);
    float li = ea * sinf(w);
    float zr = zt[m * 256 + c];
    float zi = zt[m * 256 + 128 + c];
    out[m * 256 + c]       = lr * zr - li * zi + g_zincr_r[idx];
    out[m * 256 + 128 + c] = lr * zi + li * zr + g_zincr_i[idx];
}

__global__ void yt_combine_kernel(float* __restrict__ out)
{
    int idx = blockIdx.x * blockDim.x + threadIdx.x;
    if (idx >= BATCH * NY) return;
    out[BATCH * LATENT + idx] = g_ytr[idx] - g_yti[idx] + g_ytd[idx];
}

extern "C" void kernel_launch(void* const* d_in, const int* in_sizes, int n_in,
                              void* d_out, int out_size)
{
    const float* zt      = (const float*)d_in[0];
    const float* dt      = (const float*)d_in[1];
    const float* ut      = (const float*)d_in[2];
    const float* sel_w0  = (const float*)d_in[3];
    const float* sel_b0  = (const float*)d_in[4];
    const float* sel_g0  = (const float*)d_in[5];
    const float* sel_be0 = (const float*)d_in[6];
    const float* sel_w1  = (const float*)d_in[7];
    const float* sel_b1  = (const float*)d_in[8];
    const float* sel_g1  = (const float*)d_in[9];
    const float* sel_be1 = (const float*)d_in[10];
    const float* sel_w2  = (const float*)d_in[11];
    const float* sel_b2  = (const float*)d_in[12];
    const float* alpha_w = (const float*)d_in[13];
    const float* alpha_b = (const float*)d_in[14];
    const float* omega_w = (const float*)d_in[15];
    const float* omega_b = (const float*)d_in[16];
    const float* btr_w   = (const float*)d_in[17];
    const float* btr_b   = (const float*)d_in[18];
    const float* bti_w   = (const float*)d_in[19];
    const float* bti_b   = (const float*)d_in[20];
    const float* ctr_w   = (const float*)d_in[21];
    const float* ctr_b   = (const float*)d_in[22];
    const float* cti_w   = (const float*)d_in[23];
    const float* cti_b   = (const float*)d_in[24];
    const float* dtw_w   = (const float*)d_in[25];
    const float* dtw_b   = (const float*)d_in[26];
    float* out = (float*)d_out;

    float *A0, *W0, *W1, *W2, *Wao, *Bao, *Wbtr, *Wbti, *Wctr, *Wcti, *Wdtw;
    float *x1, *x2, *hz, *ao, *zir, *zii, *ytr, *yti, *ytd;
    cudaGetSymbolAddress((void**)&A0,   g_A0);
    cudaGetSymbolAddress((void**)&W0,   g_W0);
    cudaGetSymbolAddress((void**)&W1,   g_W1);
    cudaGetSymbolAddress((void**)&W2,   g_W2);
    cudaGetSymbolAddress((void**)&Wao,  g_Wao);
    cudaGetSymbolAddress((void**)&Bao,  g_Bao);
    cudaGetSymbolAddress((void**)&Wbtr, g_Wbtr);
    cudaGetSymbolAddress((void**)&Wbti, g_Wbti);
    cudaGetSymbolAddress((void**)&Wctr, g_Wctr);
    cudaGetSymbolAddress((void**)&Wcti, g_Wcti);
    cudaGetSymbolAddress((void**)&Wdtw, g_Wdtw);
    cudaGetSymbolAddress((void**)&x1,  g_x1);
    cudaGetSymbolAddress((void**)&x2,  g_x2);
    cudaGetSymbolAddress((void**)&hz,  g_hz);
    cudaGetSymbolAddress((void**)&ao,  g_ao);
    cudaGetSymbolAddress((void**)&zir, g_zincr_r);
    cudaGetSymbolAddress((void**)&zii, g_zincr_i);
    cudaGetSymbolAddress((void**)&ytr, g_ytr);
    cudaGetSymbolAddress((void**)&yti, g_yti);
    cudaGetSymbolAddress((void**)&ytd, g_ytd);

    cudaFuncSetAttribute((const void*)gemm_tc<1,1>, cudaFuncAttributeMaxDynamicSharedMemorySize, SMEM_BYTES);
    cudaFuncSetAttribute((const void*)gemm_tc<2,1>, cudaFuncAttributeMaxDynamicSharedMemorySize, SMEM_BYTES);
    cudaFuncSetAttribute((const void*)gemm_tc<2,0>, cudaFuncAttributeMaxDynamicSharedMemorySize, SMEM_BYTES);
    cudaFuncSetAttribute((const void*)gemm_tc<3,0>, cudaFuncAttributeMaxDynamicSharedMemorySize, SMEM_BYTES);
    cudaFuncSetAttribute((const void*)gemm_tc<4,0>, cudaFuncAttributeMaxDynamicSharedMemorySize, SMEM_BYTES);
    cudaFuncSetAttribute((const void*)gemm_tc<5,0>, cudaFuncAttributeMaxDynamicSharedMemorySize, SMEM_BYTES);

    dim3 thr(NTHREADS);

    // operand prep: tf32-round weights/inputs, build concat buffers
    prep_kernel<<<2048, 256>>>(zt, dt, ut, sel_w0, sel_w1, sel_w2,
                               alpha_w, alpha_b, omega_w, omega_b,
                               btr_w, bti_w, ctr_w, cti_w, dtw_w);

    // selector MLP
    gemm_tc<1,1><<<dim3(64, 2), thr, SMEM_BYTES>>>(A0, 320, W0, 256, sel_b0,
                                                   nullptr, nullptr, sel_g0, sel_be0, x1, 256);
    gemm_tc<1,1><<<dim3(64, 2), thr, SMEM_BYTES>>>(x1, 256, W1, 256, sel_b1,
                                                   nullptr, nullptr, sel_g1, sel_be1, x2, 256);
    gemm_tc<2,1><<<dim3(64, 2), thr, SMEM_BYTES>>>(x2, 256, W2, 256, sel_b2,
                                                   nullptr, nullptr, nullptr, nullptr, hz, 256);
    // alpha|omega combined (stored fp32, unrounded — consumed by znext in fp32)
    gemm_tc<2,0><<<dim3(64, 2), thr, SMEM_BYTES>>>(hz, 256, Wao, 256, Bao,
                                                   nullptr, nullptr, nullptr, nullptr, ao, 256);
    // Bt (real, imag) fused with einsum('bcu,bu->bc')
    gemm_tc<3,0><<<dim3(64, 32), thr, SMEM_BYTES>>>(hz, 256, Wbtr, 4096, btr_b,
                                                    ut, dt, nullptr, nullptr, zir, CD);
    gemm_tc<3,0><<<dim3(64, 32), thr, SMEM_BYTES>>>(hz, 256, Wbti, 4096, bti_b,
                                                    ut, dt, nullptr, nullptr, zii, CD);
    // z_next into d_out[:, 0:256]
    znext_kernel<<<(BATCH * CD) / 256, 256>>>(zt, out);
    // Ct (real, imag) fused with einsum('byc,bc->by'); reads z_next from d_out
    gemm_tc<4,0><<<dim3(64, 50), thr, SMEM_BYTES>>>(hz, 256, Wctr, 6400, ctr_b,
                                                    out, nullptr, nullptr, nullptr, ytr, NY);
    gemm_tc<4,0><<<dim3(64, 50), thr, SMEM_BYTES>>>(hz, 256, Wcti, 6400, cti_b,
                                                    out + 128, nullptr, nullptr, nullptr, yti, NY);
    // Dt fused with einsum('byu,bu->by')
    gemm_tc<5,0><<<dim3(64, 13), thr, SMEM_BYTES>>>(hz, 256, Wdtw, 1600, dtw_b,
                                                    ut, dt, nullptr, nullptr, ytd, NY);
    // yt = Re(Ct z) + Dt utdt
    yt_combine_kernel<<<(BATCH * NY + 255) / 256, 256>>>(out);
}

// round 6
// speedup vs baseline: 4.9187x; 1.0294x over previous
#include <cuda_runtime.h>
#include <math.h>
#include <stdint.h>

#define BATCH  8192
#define LATENT 256
#define CD     128
#define UDIM   32
#define NY     50
#define NTHREADS 256
#define STAGES 3
#define STAGE_FLOATS 12288              // (128 A rows + 256 B rows) * 32 k * fp32
#define CTRLF (STAGES * STAGE_FLOATS)
#define SMEM_FLOATS (CTRLF + 1280)      // + bias(256) gamma(256) beta(256) red(512)
#define SMEM_BYTES  (SMEM_FLOATS * 4)

// ---------------- scratch (static device globals; no allocation) ----------------
// pre-rounded (tf32-rna) GEMM operands (same as R3)
__device__ float g_A0 [BATCH * 320];
__device__ float g_W0 [256 * 320];
__device__ float g_W1 [256 * 256];
__device__ float g_W2 [256 * 256];
__device__ float g_Wao[256 * 256];
__device__ float g_Bao[256];
__device__ float g_Wbtr[4096 * 256];
__device__ float g_Wbti[4096 * 256];
__device__ float g_Wctr[6400 * 256];
__device__ float g_Wcti[6400 * 256];
__device__ float g_Wdtw[1600 * 256];
__device__ float g_x1[BATCH * LATENT];
__device__ float g_x2[BATCH * LATENT];
__device__ float g_hz[BATCH * LATENT];
__device__ float g_ao[BATCH * LATENT];
__device__ float g_zincr_r[BATCH * CD];
__device__ float g_zincr_i[BATCH * CD];
__device__ float g_ytr[BATCH * NY];
__device__ float g_yti[BATCH * NY];
__device__ float g_ytd[BATCH * NY];

// ---------------- PTX helpers ----------------
__device__ __forceinline__ uint32_t f2tf32(float f) {
    uint32_t r;
    asm("cvt.rna.tf32.f32 %0, %1;" : "=r"(r) : "f"(f));
    return r;
}
__device__ __forceinline__ float rnd_tf32(float f) { return __uint_as_float(f2tf32(f)); }

__device__ __forceinline__ void ldsm4(uint32_t& a0, uint32_t& a1, uint32_t& a2, uint32_t& a3,
                                      uint32_t addr) {
    asm volatile("ldmatrix.sync.aligned.m8n8.x4.shared.b16 {%0,%1,%2,%3}, [%4];"
                 : "=r"(a0), "=r"(a1), "=r"(a2), "=r"(a3) : "r"(addr));
}
__device__ __forceinline__ void mma_tf32(float* c,
                                         uint32_t a0, uint32_t a1, uint32_t a2, uint32_t a3,
                                         uint32_t b0, uint32_t b1) {
    asm volatile(
        "mma.sync.aligned.m16n8k8.row.col.f32.tf32.tf32.f32 "
        "{%0,%1,%2,%3},{%4,%5,%6,%7},{%8,%9},{%0,%1,%2,%3};"
        : "+f"(c[0]), "+f"(c[1]), "+f"(c[2]), "+f"(c[3])
        : "r"(a0), "r"(a1), "r"(a2), "r"(a3), "r"(b0), "r"(b1));
}
__device__ __forceinline__ void cp16(uint32_t dst, const float* src, int sz) {
    asm volatile("cp.async.cg.shared.global [%0], [%1], 16, %2;"
                 :: "r"(dst), "l"(src), "r"(sz));
}

// ---------------- prep: tf32-round all GEMM operands (identical to R3) ----------
#define E_A0  (BATCH * 320)
#define E_W0  (E_A0  + 256 * 320)
#define E_W1  (E_W0  + 65536)
#define E_W2  (E_W1  + 65536)
#define E_WAO (E_W2  + 65536)
#define E_BAO (E_WAO + 256)
#define E_BTR (E_BAO + 4096 * 256)
#define E_BTI (E_BTR + 4096 * 256)
#define E_CTR (E_BTI + 6400 * 256)
#define E_CTI (E_CTR + 6400 * 256)
#define E_DTW (E_CTI + 1600 * 256)

__global__ void prep_kernel(const float* __restrict__ zt, const float* __restrict__ dt,
                            const float* __restrict__ ut,
                            const float* __restrict__ sw0, const float* __restrict__ sw1,
                            const float* __restrict__ sw2,
                            const float* __restrict__ aw, const float* __restrict__ ab,
                            const float* __restrict__ ow, const float* __restrict__ ob,
                            const float* __restrict__ btr, const float* __restrict__ bti,
                            const float* __restrict__ ctr, const float* __restrict__ cti,
                            const float* __restrict__ dtw)
{
    for (int idx = blockIdx.x * blockDim.x + threadIdx.x; idx < E_DTW;
         idx += gridDim.x * blockDim.x) {
        if (idx < E_A0) {
            int m = idx / 320, c = idx % 320;
            float v = 0.f;
            if (c < 256)       v = zt[m * 256 + c];
            else if (c < 288)  v = ut[m * UDIM + (c - 256)];
            else if (c == 288) v = dt[m];
            g_A0[idx] = rnd_tf32(v);
        } else if (idx < E_W0) {
            int j = idx - E_A0;
            int r = j / 320, c = j % 320;
            g_W0[j] = (c < 289) ? rnd_tf32(sw0[r * 289 + c]) : 0.f;
        } else if (idx < E_W1) {
            int j = idx - E_W0;  g_W1[j] = rnd_tf32(sw1[j]);
        } else if (idx < E_W2) {
            int j = idx - E_W1;  g_W2[j] = rnd_tf32(sw2[j]);
        } else if (idx < E_WAO) {
            int j = idx - E_W2;
            g_Wao[j] = rnd_tf32((j < 128 * 256) ? aw[j] : ow[j - 128 * 256]);
        } else if (idx < E_BAO) {
            int j = idx - E_WAO;
            g_Bao[j] = (j < 128) ? ab[j] : ob[j - 128];
        } else if (idx < E_BTR) {
            int j = idx - E_BAO; g_Wbtr[j] = rnd_tf32(btr[j]);
        } else if (idx < E_BTI) {
            int j = idx - E_BTR; g_Wbti[j] = rnd_tf32(bti[j]);
        } else if (idx < E_CTR) {
            int j = idx - E_BTI; g_Wctr[j] = rnd_tf32(ctr[j]);
        } else if (idx < E_CTI) {
            int j = idx - E_CTR; g_Wcti[j] = rnd_tf32(cti[j]);
        } else {
            int j = idx - E_CTI; g_Wdtw[j] = rnd_tf32(dtw[j]);
        }
    }
}

// ---------------------------------------------------------------------------
// mma.sync tf32 fused GEMM: C = A[M,K] @ W[N,K]^T (+bias).
// CTA tile 128(M) x 256(N), BK=32, 3-stage cp.async, ONE sync per chunk.
// 8 warps as 2(m) x 4(n); warp tile 64 x 64 (mt=4 x nt=8 frags, acc 128 regs).
//   MODE 1: BN(eval)+ReLU  (ROUND: tf32-round store), ldc=256
//   MODE 2: +bias store (ROUND optional), ldc=256
//   MODE 3: +bias, contract 32-col u-groups with ut*dt (8 groups/tile), ldc=128
//   MODE 4: +bias, contract 128-col y-groups with zv   (2 y/tile), ldc=NY
//   MODE 5: MODE 3 with group bounds (Dt), ldc=NY
// ---------------------------------------------------------------------------
template <int MODE, int ROUND>
__global__ __launch_bounds__(NTHREADS)
void gemm_tc(const float* __restrict__ A, int K,
             const float* __restrict__ W, int N,
             const float* __restrict__ bias,
             const float* __restrict__ p0,   // ut (3/5) | zv base (4)
             const float* __restrict__ p1,   // dt (3/5)
             const float* __restrict__ p2,   // bn gamma (1)
             const float* __restrict__ p3,   // bn beta  (1)
             float* __restrict__ C, int ldc)
{
    extern __shared__ float sm[];
    const uint32_t* smb = (const uint32_t*)sm;
    float* sbias = sm + CTRLF;
    float* sg    = sbias + 256;
    float* sbe   = sg + 256;
    float* red   = sbe + 256;

    const int tid  = threadIdx.x;
    const int lane = tid & 31;
    const int warp = tid >> 5;
    const int m0 = blockIdx.x * 128;
    const int n0 = blockIdx.y * 256;
    const int wm = warp >> 2;           // 0..1 (64 rows each)
    const int wn = warp & 3;            // 0..3 (64 cols each)
    const int gq = lane >> 2;
    const int tq = lane & 3;
    const uint32_t smu = (uint32_t)__cvta_generic_to_shared(sm);

    {   // bias/BN params into smem
        int n = n0 + tid;
        sbias[tid] = (n < N) ? bias[n] : 0.f;
        if (MODE == 1) {
            sg[tid]  = p2[n] * rsqrtf(1.f + 1e-5f);
            sbe[tid] = p3[n];
        }
    }

    float acc[4][8][4];
#pragma unroll
    for (int i = 0; i < 4; i++)
#pragma unroll
        for (int j = 0; j < 8; j++)
#pragma unroll
            for (int r = 0; r < 4; r++) acc[i][j][r] = 0.f;

    // ldmatrix lane addressing (same scheme as R3)
    const int row_off = lane & 15;
    const int hi = lane >> 4;
    uint32_t abyte[4]; int arx[4];
#pragma unroll
    for (int mt = 0; mt < 4; mt++) {
        int r = wm * 64 + mt * 16 + row_off;
        abyte[mt] = smu + (uint32_t)(r * 128);
        arx[mt] = r & 7;
    }
    int bidx[8], bx[8];
#pragma unroll
    for (int nt = 0; nt < 8; nt++) {
        int n = wn * 64 + nt * 8 + gq;
        bidx[nt] = n * 32 + tq;
        bx[nt] = n & 7;
    }

    auto issue = [&](int kc, int s) {
#pragma unroll
        for (int i = 0; i < 12; i++) {
            int idx = tid + i * 256;            // 0..3071
            int r = idx >> 3, k4 = idx & 7;
            uint32_t dst; const float* src; int sz = 16;
            if (r < 128) {
                dst = smu + (uint32_t)((s * STAGE_FLOATS + r * 32 + ((k4 ^ (r & 7)) << 2)) * 4);
                src = A + (size_t)(m0 + r) * K + kc * 32 + k4 * 4;
            } else {
                int rb = r - 128;
                dst = smu + (uint32_t)((s * STAGE_FLOATS + 4096 + rb * 32 + ((k4 ^ (rb & 7)) << 2)) * 4);
                int n = n0 + rb;
                if (n < N) src = W + (size_t)n * K + kc * 32 + k4 * 4;
                else { src = W; sz = 0; }
            }
            cp16(dst, src, sz);
        }
        asm volatile("cp.async.commit_group;" ::: "memory");
    };

    auto compute = [&](int s) {
        const uint32_t sa = (uint32_t)(s * STAGE_FLOATS * 4);
        const int sbf = s * STAGE_FLOATS + 4096;
#pragma unroll
        for (int ks = 0; ks < 4; ks++) {
            uint32_t bf0[8], bf1[8];
#pragma unroll
            for (int nt = 0; nt < 8; nt++) {
                bf0[nt] = smb[sbf + bidx[nt] + (((2 * ks)     ^ bx[nt]) << 2)];
                bf1[nt] = smb[sbf + bidx[nt] + (((2 * ks + 1) ^ bx[nt]) << 2)];
            }
            const int k4a = 2 * ks + hi;
#pragma unroll
            for (int mt = 0; mt < 4; mt++) {
                uint32_t a0, a1, a2, a3;
                ldsm4(a0, a1, a2, a3, abyte[mt] + sa + (uint32_t)((k4a ^ arx[mt]) << 4));
#pragma unroll
                for (int nt = 0; nt < 8; nt++)
                    mma_tf32(acc[mt][nt], a0, a1, a2, a3, bf0[nt], bf1[nt]);
            }
        }
    };

    const int NC = K >> 5;
    issue(0, 0);
    issue(1, 1);
    for (int kc = 0; kc < NC; kc++) {
        asm volatile("cp.async.wait_group 1;" ::: "memory");
        __syncthreads();
        int pf = kc + 2;
        if (pf < NC) issue(pf, pf % STAGES);
        else asm volatile("cp.async.commit_group;" ::: "memory");
        compute(kc % STAGES);
    }

    // ---------------- epilogues ----------------
    // acc r=h*2+p -> m = m0+wm*64+mt*16+gq+h*8 ; n = n0+wn*64+nt*8+tq*2+p
    if (MODE <= 2) {
#pragma unroll
        for (int nt = 0; nt < 8; nt++)
#pragma unroll
            for (int p = 0; p < 2; p++) {
                int nl = wn * 64 + nt * 8 + tq * 2 + p;
                int n = n0 + nl;
                float bi = sbias[nl];
                float gg = (MODE == 1) ? sg[nl] : 0.f;
                float bb = (MODE == 1) ? sbe[nl] : 0.f;
#pragma unroll
                for (int mt = 0; mt < 4; mt++)
#pragma unroll
                    for (int h = 0; h < 2; h++) {
                        int m = m0 + wm * 64 + mt * 16 + gq + h * 8;
                        float v = acc[mt][nt][h * 2 + p] + bi;
                        if (MODE == 1) v = fmaxf(v * gg + bb, 0.f);
                        C[(size_t)m * ldc + n] = ROUND ? rnd_tf32(v) : v;
                    }
            }
    } else if (MODE == 3 || MODE == 5) {
        // warp's 64 cols = 2 u-groups of 32; contraction completes in-warp
#pragma unroll
        for (int g = 0; g < 2; g++) {
            int gcol = blockIdx.y * 8 + wn * 2 + g;
            bool gvalid = (MODE == 3) || (gcol < NY);
#pragma unroll
            for (int mt = 0; mt < 4; mt++)
#pragma unroll
                for (int h = 0; h < 2; h++) {
                    int m = m0 + wm * 64 + mt * 16 + gq + h * 8;
                    float s = 0.f;
#pragma unroll
                    for (int j = 0; j < 4; j++) {
                        int nt = g * 4 + j;
#pragma unroll
                        for (int p = 0; p < 2; p++) {
                            int u = j * 8 + tq * 2 + p;
                            int nl = wn * 64 + nt * 8 + tq * 2 + p;
                            s += (acc[mt][nt][h * 2 + p] + sbias[nl])
                                 * p0[(size_t)m * UDIM + u];
                        }
                    }
                    s += __shfl_xor_sync(0xffffffffu, s, 1);
                    s += __shfl_xor_sync(0xffffffffu, s, 2);
                    if (tq == 0 && gvalid)
                        C[(size_t)m * ldc + gcol] = s * p1[m];
                }
        }
    } else {  // MODE 4: tile's 256 cols = 2 y-groups of 128; contract with zv
        const int y = wn >> 1, half = wn & 1;
#pragma unroll
        for (int mt = 0; mt < 4; mt++)
#pragma unroll
            for (int h = 0; h < 2; h++) {
                int rl = wm * 64 + mt * 16 + gq + h * 8;
                int m = m0 + rl;
                float s = 0.f;
#pragma unroll
                for (int nt = 0; nt < 8; nt++)
#pragma unroll
                    for (int p = 0; p < 2; p++) {
                        int cl = half * 64 + nt * 8 + tq * 2 + p;
                        int nl = wn * 64 + nt * 8 + tq * 2 + p;
                        s += (acc[mt][nt][h * 2 + p] + sbias[nl])
                             * p0[(size_t)m * 256 + cl];
                    }
                s += __shfl_xor_sync(0xffffffffu, s, 1);
                s += __shfl_xor_sync(0xffffffffu, s, 2);
                if (tq == 0)
                    red[rl * 4 + y * 2 + half] = s;
            }
        __syncthreads();
        if (tid < 128) {
            int m = m0 + tid;
#pragma unroll
            for (int y2 = 0; y2 < 2; y2++)
                C[(size_t)m * ldc + blockIdx.y * 2 + y2] =
                    red[tid * 4 + y2 * 2] + red[tid * 4 + y2 * 2 + 1];
        }
    }
}

// z_next = exp(-softplus(a) + i*omega) * z + zincr
__global__ void znext_kernel(const float* __restrict__ zt, float* __restrict__ out)
{
    int idx = blockIdx.x * blockDim.x + threadIdx.x;
    if (idx >= BATCH * CD) return;
    int m = idx >> 7, c = idx & 127;
    float a = g_ao[m * 256 + c];
    float w = g_ao[m * 256 + 128 + c];
    float ea = 1.f / (1.f + expf(a));
    float lr = ea * cosf(w);
    float li = ea * sinf(w);
    float zr = zt[m * 256 + c];
    float zi = zt[m * 256 + 128 + c];
    out[m * 256 + c]       = lr * zr - li * zi + g_zincr_r[idx];
    out[m * 256 + 128 + c] = lr * zi + li * zr + g_zincr_i[idx];
}

__global__ void yt_combine_kernel(float* __restrict__ out)
{
    int idx = blockIdx.x * blockDim.x + threadIdx.x;
    if (idx >= BATCH * NY) return;
    out[BATCH * LATENT + idx] = g_ytr[idx] - g_yti[idx] + g_ytd[idx];
}

// ================================================================================
extern "C" void kernel_launch(void* const* d_in, const int* in_sizes, int n_in,
                              void* d_out, int out_size)
{
    const float* zt      = (const float*)d_in[0];
    const float* dt      = (const float*)d_in[1];
    const float* ut      = (const float*)d_in[2];
    const float* sel_w0  = (const float*)d_in[3];
    const float* sel_b0  = (const float*)d_in[4];
    const float* sel_g0  = (const float*)d_in[5];
    const float* sel_be0 = (const float*)d_in[6];
    const float* sel_w1  = (const float*)d_in[7];
    const float* sel_b1  = (const float*)d_in[8];
    const float* sel_g1  = (const float*)d_in[9];
    const float* sel_be1 = (const float*)d_in[10];
    const float* sel_w2  = (const float*)d_in[11];
    const float* sel_b2  = (const float*)d_in[12];
    const float* alpha_w = (const float*)d_in[13];
    const float* alpha_b = (const float*)d_in[14];
    const float* omega_w = (const float*)d_in[15];
    const float* omega_b = (const float*)d_in[16];
    const float* btr_w   = (const float*)d_in[17];
    const float* btr_b   = (const float*)d_in[18];
    const float* bti_w   = (const float*)d_in[19];
    const float* bti_b   = (const float*)d_in[20];
    const float* ctr_w   = (const float*)d_in[21];
    const float* ctr_b   = (const float*)d_in[22];
    const float* cti_w   = (const float*)d_in[23];
    const float* cti_b   = (const float*)d_in[24];
    const float* dtw_w   = (const float*)d_in[25];
    const float* dtw_b   = (const float*)d_in[26];
    float* out = (float*)d_out;

    float *A0, *W0, *W1, *W2, *Wao, *Bao, *Wbtr, *Wbti, *Wctr, *Wcti, *Wdtw;
    float *x1, *x2, *hz, *ao, *zir, *zii, *ytr, *yti, *ytd;
    cudaGetSymbolAddress((void**)&A0,   g_A0);
    cudaGetSymbolAddress((void**)&W0,   g_W0);
    cudaGetSymbolAddress((void**)&W1,   g_W1);
    cudaGetSymbolAddress((void**)&W2,   g_W2);
    cudaGetSymbolAddress((void**)&Wao,  g_Wao);
    cudaGetSymbolAddress((void**)&Bao,  g_Bao);
    cudaGetSymbolAddress((void**)&Wbtr, g_Wbtr);
    cudaGetSymbolAddress((void**)&Wbti, g_Wbti);
    cudaGetSymbolAddress((void**)&Wctr, g_Wctr);
    cudaGetSymbolAddress((void**)&Wcti, g_Wcti);
    cudaGetSymbolAddress((void**)&Wdtw, g_Wdtw);
    cudaGetSymbolAddress((void**)&x1,  g_x1);
    cudaGetSymbolAddress((void**)&x2,  g_x2);
    cudaGetSymbolAddress((void**)&hz,  g_hz);
    cudaGetSymbolAddress((void**)&ao,  g_ao);
    cudaGetSymbolAddress((void**)&zir, g_zincr_r);
    cudaGetSymbolAddress((void**)&zii, g_zincr_i);
    cudaGetSymbolAddress((void**)&ytr, g_ytr);
    cudaGetSymbolAddress((void**)&yti, g_yti);
    cudaGetSymbolAddress((void**)&ytd, g_ytd);

    cudaFuncSetAttribute((const void*)gemm_tc<1,1>, cudaFuncAttributeMaxDynamicSharedMemorySize, SMEM_BYTES);
    cudaFuncSetAttribute((const void*)gemm_tc<2,1>, cudaFuncAttributeMaxDynamicSharedMemorySize, SMEM_BYTES);
    cudaFuncSetAttribute((const void*)gemm_tc<2,0>, cudaFuncAttributeMaxDynamicSharedMemorySize, SMEM_BYTES);
    cudaFuncSetAttribute((const void*)gemm_tc<3,0>, cudaFuncAttributeMaxDynamicSharedMemorySize, SMEM_BYTES);
    cudaFuncSetAttribute((const void*)gemm_tc<4,0>, cudaFuncAttributeMaxDynamicSharedMemorySize, SMEM_BYTES);
    cudaFuncSetAttribute((const void*)gemm_tc<5,0>, cudaFuncAttributeMaxDynamicSharedMemorySize, SMEM_BYTES);

    dim3 thr(NTHREADS);

    prep_kernel<<<2048, 256>>>(zt, dt, ut, sel_w0, sel_w1, sel_w2,
                               alpha_w, alpha_b, omega_w, omega_b,
                               btr_w, bti_w, ctr_w, cti_w, dtw_w);

    // selector MLP (N=256 -> single tile column)
    gemm_tc<1,1><<<dim3(64, 1), thr, SMEM_BYTES>>>(A0, 320, W0, 256, sel_b0,
                                                   nullptr, nullptr, sel_g0, sel_be0, x1, 256);
    gemm_tc<1,1><<<dim3(64, 1), thr, SMEM_BYTES>>>(x1, 256, W1, 256, sel_b1,
                                                   nullptr, nullptr, sel_g1, sel_be1, x2, 256);
    gemm_tc<2,1><<<dim3(64, 1), thr, SMEM_BYTES>>>(x2, 256, W2, 256, sel_b2,
                                                   nullptr, nullptr, nullptr, nullptr, hz, 256);
    // alpha|omega combined (fp32 out, unrounded)
    gemm_tc<2,0><<<dim3(64, 1), thr, SMEM_BYTES>>>(hz, 256, Wao, 256, Bao,
                                                   nullptr, nullptr, nullptr, nullptr, ao, 256);
    // Bt (real, imag) fused with einsum('bcu,bu->bc')
    gemm_tc<3,0><<<dim3(64, 16), thr, SMEM_BYTES>>>(hz, 256, Wbtr, 4096, btr_b,
                                                    ut, dt, nullptr, nullptr, zir, CD);
    gemm_tc<3,0><<<dim3(64, 16), thr, SMEM_BYTES>>>(hz, 256, Wbti, 4096, bti_b,
                                                    ut, dt, nullptr, nullptr, zii, CD);
    // z_next into d_out[:, 0:256]
    znext_kernel<<<(BATCH * CD) / 256, 256>>>(zt, out);
    // Ct (real, imag) fused with einsum('byc,bc->by'); reads z_next from d_out
    gemm_tc<4,0><<<dim3(64, 25), thr, SMEM_BYTES>>>(hz, 256, Wctr, 6400, ctr_b,
                                                    out, nullptr, nullptr, nullptr, ytr, NY);
    gemm_tc<4,0><<<dim3(64, 25), thr, SMEM_BYTES>>>(hz, 256, Wcti, 6400, cti_b,
                                                    out + 128, nullptr, nullptr, nullptr, yti, NY);
    // Dt fused with einsum('byu,bu->by')
    gemm_tc<5,0><<<dim3(64, 7), thr, SMEM_BYTES>>>(hz, 256, Wdtw, 1600, dtw_b,
                                                   ut, dt, nullptr, nullptr, ytd, NY);
    // yt = Re(Ct z) + Dt utdt
    yt_combine_kernel<<<(BATCH * NY + 255) / 256, 256>>>(out);
}

// round 7
// speedup vs baseline: 5.1902x; 1.0552x over previous
#include <cuda_runtime.h>
#include <math.h>
#include <stdint.h>

#define BATCH  8192
#define LATENT 256
#define CD     128
#define UDIM   32
#define NY     50
#define NTH    512

// ---------------- scratch (static device globals; no allocation) ----------------
__device__ float g_A0 [BATCH * 320];
__device__ float g_W0 [256 * 320];
__device__ float g_W1 [256 * 256];
__device__ float g_W2 [256 * 256];
__device__ float g_Wao[256 * 256];
__device__ float g_Bao[256];
__device__ float g_Wbtr[4096 * 256];
__device__ float g_Wbti[4096 * 256];
__device__ float g_Wctr[6400 * 256];
__device__ float g_Wcti[6400 * 256];
__device__ float g_Wdtw[1600 * 256];
__device__ float g_x1[BATCH * LATENT];
__device__ float g_x2[BATCH * LATENT];
__device__ float g_hz[BATCH * LATENT];
__device__ float g_ao[BATCH * LATENT];
__device__ float g_zincr_r[BATCH * CD];
__device__ float g_zincr_i[BATCH * CD];
__device__ float g_ytr[BATCH * NY];
__device__ float g_yti[BATCH * NY];
__device__ float g_ytd[BATCH * NY];

// ---------------- PTX helpers ----------------
__device__ __forceinline__ uint32_t f2tf32(float f) {
    uint32_t r;
    asm("cvt.rna.tf32.f32 %0, %1;" : "=r"(r) : "f"(f));
    return r;
}
__device__ __forceinline__ float rnd_tf32(float f) { return __uint_as_float(f2tf32(f)); }

__device__ __forceinline__ void ldsm4(uint32_t& a0, uint32_t& a1, uint32_t& a2, uint32_t& a3,
                                      uint32_t addr) {
    asm volatile("ldmatrix.sync.aligned.m8n8.x4.shared.b16 {%0,%1,%2,%3}, [%4];"
                 : "=r"(a0), "=r"(a1), "=r"(a2), "=r"(a3) : "r"(addr));
}
__device__ __forceinline__ void mma_tf32(float* c,
                                         uint32_t a0, uint32_t a1, uint32_t a2, uint32_t a3,
                                         uint32_t b0, uint32_t b1) {
    asm volatile(
        "mma.sync.aligned.m16n8k8.row.col.f32.tf32.tf32.f32 "
        "{%0,%1,%2,%3},{%4,%5,%6,%7},{%8,%9},{%0,%1,%2,%3};"
        : "+f"(c[0]), "+f"(c[1]), "+f"(c[2]), "+f"(c[3])
        : "r"(a0), "r"(a1), "r"(a2), "r"(a3), "r"(b0), "r"(b1));
}
__device__ __forceinline__ void cp16(uint32_t dst, const float* src, int sz) {
    asm volatile("cp.async.cg.shared.global [%0], [%1], 16, %2;"
                 :: "r"(dst), "l"(src), "r"(sz));
}

// ---------------- prep (identical numerics to R3/R6) ----------------
#define E_A0  (BATCH * 320)
#define E_W0  (E_A0  + 256 * 320)
#define E_W1  (E_W0  + 65536)
#define E_W2  (E_W1  + 65536)
#define E_WAO (E_W2  + 65536)
#define E_BAO (E_WAO + 256)
#define E_BTR (E_BAO + 4096 * 256)
#define E_BTI (E_BTR + 4096 * 256)
#define E_CTR (E_BTI + 6400 * 256)
#define E_CTI (E_CTR + 6400 * 256)
#define E_DTW (E_CTI + 1600 * 256)

__global__ void prep_kernel(const float* __restrict__ zt, const float* __restrict__ dt,
                            const float* __restrict__ ut,
                            const float* __restrict__ sw0, const float* __restrict__ sw1,
                            const float* __restrict__ sw2,
                            const float* __restrict__ aw, const float* __restrict__ ab,
                            const float* __restrict__ ow, const float* __restrict__ ob,
                            const float* __restrict__ btr, const float* __restrict__ bti,
                            const float* __restrict__ ctr, const float* __restrict__ cti,
                            const float* __restrict__ dtw)
{
    for (int idx = blockIdx.x * blockDim.x + threadIdx.x; idx < E_DTW;
         idx += gridDim.x * blockDim.x) {
        if (idx < E_A0) {
            int m = idx / 320, c = idx % 320;
            float v = 0.f;
            if (c < 256)       v = zt[m * 256 + c];
            else if (c < 288)  v = ut[m * UDIM + (c - 256)];
            else if (c == 288) v = dt[m];
            g_A0[idx] = rnd_tf32(v);
        } else if (idx < E_W0) {
            int j = idx - E_A0;
            int r = j / 320, c = j % 320;
            g_W0[j] = (c < 289) ? rnd_tf32(sw0[r * 289 + c]) : 0.f;
        } else if (idx < E_W1) {
            int j = idx - E_W0;  g_W1[j] = rnd_tf32(sw1[j]);
        } else if (idx < E_W2) {
            int j = idx - E_W1;  g_W2[j] = rnd_tf32(sw2[j]);
        } else if (idx < E_WAO) {
            int j = idx - E_W2;
            g_Wao[j] = rnd_tf32((j < 128 * 256) ? aw[j] : ow[j - 128 * 256]);
        } else if (idx < E_BAO) {
            int j = idx - E_WAO;
            g_Bao[j] = (j < 128) ? ab[j] : ob[j - 128];
        } else if (idx < E_BTR) {
            int j = idx - E_BAO; g_Wbtr[j] = rnd_tf32(btr[j]);
        } else if (idx < E_BTI) {
            int j = idx - E_BTR; g_Wbti[j] = rnd_tf32(bti[j]);
        } else if (idx < E_CTR) {
            int j = idx - E_BTI; g_Wctr[j] = rnd_tf32(ctr[j]);
        } else if (idx < E_CTI) {
            int j = idx - E_CTR; g_Wcti[j] = rnd_tf32(cti[j]);
        } else {
            int j = idx - E_CTI; g_Wdtw[j] = rnd_tf32(dtw[j]);
        }
    }
}

// ---------------------------------------------------------------------------
// mma.sync tf32 fused GEMM, 512 threads (16 warps -> 4 per SMSP).
// CTA tile 128(M) x BN(N), BK=32, 3-stage cp.async, one sync per chunk.
// Warps: wm = warp>>3 (2 M-groups of 64), wn = warp&7 (8 N-groups of BN/8).
// Warp tile 64 x (BN/8): mt=4 m-frags, NT=BN/64 n-frags, acc = 16*NT regs.
//   MODE 1 (BN=128): BN(eval)+ReLU, ROUND, ldc=256
//   MODE 2 (BN=128): +bias store, ldc=256
//   MODE 3 (BN=256): +bias, contract 32-col u-groups with ut*dt (8 groups/tile)
//   MODE 4 (BN=256): +bias, contract 128-col y-groups with zv   (2 y/tile)
//   MODE 5 (BN=256): MODE 3 with group bounds (Dt)
// ---------------------------------------------------------------------------
template <int MODE, int ROUND, int BN>
__global__ __launch_bounds__(NTH)
void gemm_tc(const float* __restrict__ A, int K,
             const float* __restrict__ W, int N,
             const float* __restrict__ bias,
             const float* __restrict__ p0,   // ut (3/5) | zv base (4)
             const float* __restrict__ p1,   // dt (3/5)
             const float* __restrict__ p2,   // bn gamma (1)
             const float* __restrict__ p3,   // bn beta  (1)
             float* __restrict__ C, int ldc)
{
    constexpr int WN = BN / 8;          // cols per warp
    constexpr int NT = WN / 8;          // n-frags per warp
    constexpr int STG = (128 + BN) * 32;   // floats per stage
    constexpr int CTRLF = 3 * STG;

    extern __shared__ float sm[];
    const uint32_t* smb = (const uint32_t*)sm;
    float* sbias = sm + CTRLF;
    float* sg    = sbias + 256;
    float* sbe   = sg + 256;
    float* red   = sbe + 256;           // 1024 floats (MODE 4)

    const int tid  = threadIdx.x;
    const int lane = tid & 31;
    const int warp = tid >> 5;
    const int m0 = blockIdx.x * 128;
    const int n0 = blockIdx.y * BN;
    const int wm = warp >> 3;           // 0..1
    const int wn = warp & 7;            // 0..7
    const int gq = lane >> 2;
    const int tq = lane & 3;
    const uint32_t smu = (uint32_t)__cvta_generic_to_shared(sm);

    if (tid < BN) {
        int n = n0 + tid;
        sbias[tid] = (n < N) ? bias[n] : 0.f;
        if (MODE == 1) {
            sg[tid]  = p2[n] * rsqrtf(1.f + 1e-5f);
            sbe[tid] = p3[n];
        }
    }

    float acc[4][NT][4];
#pragma unroll
    for (int i = 0; i < 4; i++)
#pragma unroll
        for (int j = 0; j < NT; j++)
#pragma unroll
            for (int r = 0; r < 4; r++) acc[i][j][r] = 0.f;

    const int row_off = lane & 15;
    const int hi = lane >> 4;
    uint32_t abyte[4]; int arx[4];
#pragma unroll
    for (int mt = 0; mt < 4; mt++) {
        int r = wm * 64 + mt * 16 + row_off;
        abyte[mt] = smu + (uint32_t)(r * 128);
        arx[mt] = r & 7;
    }
    int bidx[NT], bx[NT];
#pragma unroll
    for (int nt = 0; nt < NT; nt++) {
        int n = wn * WN + nt * 8 + gq;
        bidx[nt] = n * 32 + tq;
        bx[nt] = n & 7;
    }

    auto issue = [&](int kc, int s) {
        const int tot = (128 + BN) * 8;
#pragma unroll
        for (int i = tid; i < tot; i += NTH) {
            int r = i >> 3, k4 = i & 7;
            uint32_t dst; const float* src; int sz = 16;
            if (r < 128) {
                dst = smu + (uint32_t)((s * STG + r * 32 + ((k4 ^ (r & 7)) << 2)) * 4);
                src = A + (size_t)(m0 + r) * K + kc * 32 + k4 * 4;
            } else {
                int rb = r - 128;
                dst = smu + (uint32_t)((s * STG + 4096 + rb * 32 + ((k4 ^ (rb & 7)) << 2)) * 4);
                int n = n0 + rb;
                if (n < N) src = W + (size_t)n * K + kc * 32 + k4 * 4;
                else { src = W; sz = 0; }
            }
            cp16(dst, src, sz);
        }
        asm volatile("cp.async.commit_group;" ::: "memory");
    };

    auto compute = [&](int s) {
        const uint32_t sa = (uint32_t)(s * STG * 4);
        const int sbf = s * STG + 4096;
#pragma unroll
        for (int ks = 0; ks < 4; ks++) {
            uint32_t bf0[NT], bf1[NT];
#pragma unroll
            for (int nt = 0; nt < NT; nt++) {
                bf0[nt] = smb[sbf + bidx[nt] + (((2 * ks)     ^ bx[nt]) << 2)];
                bf1[nt] = smb[sbf + bidx[nt] + (((2 * ks + 1) ^ bx[nt]) << 2)];
            }
            const int k4a = 2 * ks + hi;
#pragma unroll
            for (int mt = 0; mt < 4; mt++) {
                uint32_t a0, a1, a2, a3;
                ldsm4(a0, a1, a2, a3, abyte[mt] + sa + (uint32_t)((k4a ^ arx[mt]) << 4));
#pragma unroll
                for (int nt = 0; nt < NT; nt++)
                    mma_tf32(acc[mt][nt], a0, a1, a2, a3, bf0[nt], bf1[nt]);
            }
        }
    };

    const int NC = K >> 5;
    issue(0, 0);
    issue(1, 1);
    for (int kc = 0; kc < NC; kc++) {
        asm volatile("cp.async.wait_group 1;" ::: "memory");
        __syncthreads();
        int pf = kc + 2;
        if (pf < NC) issue(pf, pf % 3);
        else asm volatile("cp.async.commit_group;" ::: "memory");
        compute(kc % 3);
    }

    // ---------------- epilogues ----------------
    // acc r=h*2+p -> m = m0+wm*64+mt*16+gq+h*8 ; tile col nl = wn*WN+nt*8+tq*2+p
    if (MODE <= 2) {
#pragma unroll
        for (int nt = 0; nt < NT; nt++)
#pragma unroll
            for (int p = 0; p < 2; p++) {
                int nl = wn * WN + nt * 8 + tq * 2 + p;
                int n = n0 + nl;
                float bi = sbias[nl];
                float gg = (MODE == 1) ? sg[nl] : 0.f;
                float bb = (MODE == 1) ? sbe[nl] : 0.f;
#pragma unroll
                for (int mt = 0; mt < 4; mt++)
#pragma unroll
                    for (int h = 0; h < 2; h++) {
                        int m = m0 + wm * 64 + mt * 16 + gq + h * 8;
                        float v = acc[mt][nt][h * 2 + p] + bi;
                        if (MODE == 1) v = fmaxf(v * gg + bb, 0.f);
                        C[(size_t)m * ldc + n] = ROUND ? rnd_tf32(v) : v;
                    }
            }
    } else if (MODE == 3 || MODE == 5) {
        // BN=256: warp's 32 cols = exactly one u-group; in-warp contraction
        const int gcol = blockIdx.y * 8 + wn;
        const bool gvalid = (MODE == 3) || (gcol < NY);
#pragma unroll
        for (int mt = 0; mt < 4; mt++)
#pragma unroll
            for (int h = 0; h < 2; h++) {
                int m = m0 + wm * 64 + mt * 16 + gq + h * 8;
                float s = 0.f;
#pragma unroll
                for (int nt = 0; nt < NT; nt++)
#pragma unroll
                    for (int p = 0; p < 2; p++) {
                        int u = nt * 8 + tq * 2 + p;
                        s += (acc[mt][nt][h * 2 + p] + sbias[wn * 32 + u])
                             * p0[(size_t)m * UDIM + u];
                    }
                s += __shfl_xor_sync(0xffffffffu, s, 1);
                s += __shfl_xor_sync(0xffffffffu, s, 2);
                if (tq == 0 && gvalid)
                    C[(size_t)m * ldc + gcol] = s * p1[m];
            }
    } else {  // MODE 4 (BN=256): 2 y-groups of 128 cols; warp covers 32 cols
        const int cq = wn & 3;          // 32-col chunk within the 128-col y-group
#pragma unroll
        for (int mt = 0; mt < 4; mt++)
#pragma unroll
            for (int h = 0; h < 2; h++) {
                int rl = wm * 64 + mt * 16 + gq + h * 8;
                int m = m0 + rl;
                float s = 0.f;
#pragma unroll
                for (int nt = 0; nt < NT; nt++)
#pragma unroll
                    for (int p = 0; p < 2; p++) {
                        int cl = cq * 32 + nt * 8 + tq * 2 + p;
                        int nl = wn * 32 + nt * 8 + tq * 2 + p;
                        s += (acc[mt][nt][h * 2 + p] + sbias[nl])
                             * p0[(size_t)m * 256 + cl];
                    }
                s += __shfl_xor_sync(0xffffffffu, s, 1);
                s += __shfl_xor_sync(0xffffffffu, s, 2);
                if (tq == 0)
                    red[rl * 8 + wn] = s;
            }
        __syncthreads();
        if (tid < 256) {
            int rl = tid >> 1, y2 = tid & 1;
            float s = red[rl * 8 + y2 * 4] + red[rl * 8 + y2 * 4 + 1]
                    + red[rl * 8 + y2 * 4 + 2] + red[rl * 8 + y2 * 4 + 3];
            C[(size_t)(m0 + rl) * ldc + blockIdx.y * 2 + y2] = s;
        }
    }
}

// z_next = exp(-softplus(a) + i*omega) * z + zincr
__global__ void znext_kernel(const float* __restrict__ zt, float* __restrict__ out)
{
    int idx = blockIdx.x * blockDim.x + threadIdx.x;
    if (idx >= BATCH * CD) return;
    int m = idx >> 7, c = idx & 127;
    float a = g_ao[m * 256 + c];
    float w = g_ao[m * 256 + 128 + c];
    float ea = 1.f / (1.f + expf(a));
    float lr = ea * cosf(w);
    float li = ea * sinf(w);
    float zr = zt[m * 256 + c];
    float zi = zt[m * 256 + 128 + c];
    out[m * 256 + c]       = lr * zr - li * zi + g_zincr_r[idx];
    out[m * 256 + 128 + c] = lr * zi + li * zr + g_zincr_i[idx];
}

__global__ void yt_combine_kernel(float* __restrict__ out)
{
    int idx = blockIdx.x * blockDim.x + threadIdx.x;
    if (idx >= BATCH * NY) return;
    out[BATCH * LATENT + idx] = g_ytr[idx] - g_yti[idx] + g_ytd[idx];
}

// ================================================================================
extern "C" void kernel_launch(void* const* d_in, const int* in_sizes, int n_in,
                              void* d_out, int out_size)
{
    const float* zt      = (const float*)d_in[0];
    const float* dt      = (const float*)d_in[1];
    const float* ut      = (const float*)d_in[2];
    const float* sel_w0  = (const float*)d_in[3];
    const float* sel_b0  = (const float*)d_in[4];
    const float* sel_g0  = (const float*)d_in[5];
    const float* sel_be0 = (const float*)d_in[6];
    const float* sel_w1  = (const float*)d_in[7];
    const float* sel_b1  = (const float*)d_in[8];
    const float* sel_g1  = (const float*)d_in[9];
    const float* sel_be1 = (const float*)d_in[10];
    const float* sel_w2  = (const float*)d_in[11];
    const float* sel_b2  = (const float*)d_in[12];
    const float* alpha_w = (const float*)d_in[13];
    const float* alpha_b = (const float*)d_in[14];
    const float* omega_w = (const float*)d_in[15];
    const float* omega_b = (const float*)d_in[16];
    const float* btr_w   = (const float*)d_in[17];
    const float* btr_b   = (const float*)d_in[18];
    const float* bti_w   = (const float*)d_in[19];
    const float* bti_b   = (const float*)d_in[20];
    const float* ctr_w   = (const float*)d_in[21];
    const float* ctr_b   = (const float*)d_in[22];
    const float* cti_w   = (const float*)d_in[23];
    const float* cti_b   = (const float*)d_in[24];
    const float* dtw_w   = (const float*)d_in[25];
    const float* dtw_b   = (const float*)d_in[26];
    float* out = (float*)d_out;

    float *A0, *W0, *W1, *W2, *Wao, *Bao, *Wbtr, *Wbti, *Wctr, *Wcti, *Wdtw;
    float *x1, *x2, *hz, *ao, *zir, *zii, *ytr, *yti, *ytd;
    cudaGetSymbolAddress((void**)&A0,   g_A0);
    cudaGetSymbolAddress((void**)&W0,   g_W0);
    cudaGetSymbolAddress((void**)&W1,   g_W1);
    cudaGetSymbolAddress((void**)&W2,   g_W2);
    cudaGetSymbolAddress((void**)&Wao,  g_Wao);
    cudaGetSymbolAddress((void**)&Bao,  g_Bao);
    cudaGetSymbolAddress((void**)&Wbtr, g_Wbtr);
    cudaGetSymbolAddress((void**)&Wbti, g_Wbti);
    cudaGetSymbolAddress((void**)&Wctr, g_Wctr);
    cudaGetSymbolAddress((void**)&Wcti, g_Wcti);
    cudaGetSymbolAddress((void**)&Wdtw, g_Wdtw);
    cudaGetSymbolAddress((void**)&x1,  g_x1);
    cudaGetSymbolAddress((void**)&x2,  g_x2);
    cudaGetSymbolAddress((void**)&hz,  g_hz);
    cudaGetSymbolAddress((void**)&ao,  g_ao);
    cudaGetSymbolAddress((void**)&zir, g_zincr_r);
    cudaGetSymbolAddress((void**)&zii, g_zincr_i);
    cudaGetSymbolAddress((void**)&ytr, g_ytr);
    cudaGetSymbolAddress((void**)&yti, g_yti);
    cudaGetSymbolAddress((void**)&ytd, g_ytd);

    const int SMB128 = (3 * (128 + 128) * 32 + 1792) * 4;   // 104 KB
    const int SMB256 = (3 * (128 + 256) * 32 + 1792) * 4;   // 154 KB
    cudaFuncSetAttribute((const void*)gemm_tc<1,1,128>, cudaFuncAttributeMaxDynamicSharedMemorySize, SMB128);
    cudaFuncSetAttribute((const void*)gemm_tc<2,1,128>, cudaFuncAttributeMaxDynamicSharedMemorySize, SMB128);
    cudaFuncSetAttribute((const void*)gemm_tc<2,0,128>, cudaFuncAttributeMaxDynamicSharedMemorySize, SMB128);
    cudaFuncSetAttribute((const void*)gemm_tc<3,0,256>, cudaFuncAttributeMaxDynamicSharedMemorySize, SMB256);
    cudaFuncSetAttribute((const void*)gemm_tc<4,0,256>, cudaFuncAttributeMaxDynamicSharedMemorySize, SMB256);
    cudaFuncSetAttribute((const void*)gemm_tc<5,0,256>, cudaFuncAttributeMaxDynamicSharedMemorySize, SMB256);

    dim3 thr(NTH);

    prep_kernel<<<2048, 256>>>(zt, dt, ut, sel_w0, sel_w1, sel_w2,
                               alpha_w, alpha_b, omega_w, omega_b,
                               btr_w, bti_w, ctr_w, cti_w, dtw_w);

    // selector MLP (BN=128, grid (64,2) -> 128 CTAs)
    gemm_tc<1,1,128><<<dim3(64, 2), thr, SMB128>>>(A0, 320, W0, 256, sel_b0,
                                                   nullptr, nullptr, sel_g0, sel_be0, x1, 256);
    gemm_tc<1,1,128><<<dim3(64, 2), thr, SMB128>>>(x1, 256, W1, 256, sel_b1,
                                                   nullptr, nullptr, sel_g1, sel_be1, x2, 256);
    gemm_tc<2,1,128><<<dim3(64, 2), thr, SMB128>>>(x2, 256, W2, 256, sel_b2,
                                                   nullptr, nullptr, nullptr, nullptr, hz, 256);
    gemm_tc<2,0,128><<<dim3(64, 2), thr, SMB128>>>(hz, 256, Wao, 256, Bao,
                                                   nullptr, nullptr, nullptr, nullptr, ao, 256);
    // Bt (real, imag) fused with einsum('bcu,bu->bc')
    gemm_tc<3,0,256><<<dim3(64, 16), thr, SMB256>>>(hz, 256, Wbtr, 4096, btr_b,
                                                    ut, dt, nullptr, nullptr, zir, CD);
    gemm_tc<3,0,256><<<dim3(64, 16), thr, SMB256>>>(hz, 256, Wbti, 4096, bti_b,
                                                    ut, dt, nullptr, nullptr, zii, CD);
    znext_kernel<<<(BATCH * CD) / 256, 256>>>(zt, out);
    // Ct (real, imag) fused with einsum('byc,bc->by')
    gemm_tc<4,0,256><<<dim3(64, 25), thr, SMB256>>>(hz, 256, Wctr, 6400, ctr_b,
                                                    out, nullptr, nullptr, nullptr, ytr, NY);
    gemm_tc<4,0,256><<<dim3(64, 25), thr, SMB256>>>(hz, 256, Wcti, 6400, cti_b,
                                                    out + 128, nullptr, nullptr, nullptr, yti, NY);
    // Dt fused with einsum('byu,bu->by')
    gemm_tc<5,0,256><<<dim3(64, 7), thr, SMB256>>>(hz, 256, Wdtw, 1600, dtw_b,
                                                   ut, dt, nullptr, nullptr, ytd, NY);
    yt_combine_kernel<<<(BATCH * NY + 255) / 256, 256>>>(out);
}

// round 8
// speedup vs baseline: 5.4083x; 1.0420x over previous
#include <cuda_runtime.h>
#include <math.h>
#include <stdint.h>

#define BATCH  8192
#define LATENT 256
#define CD     128
#define UDIM   32
#define NY     50
#define NTH    256
#define STG    8192                      // (128 A rows + 128 B rows) * 32 k floats
#define CTRLF  (3 * STG)
#define SMEM_BYTES ((CTRLF + 1024) * 4)  // + bias(128) g(128) be(128) red(512) pad

// ---------------- scratch (static device globals; no allocation) ----------------
__device__ float g_A0 [BATCH * 320];
__device__ float g_W0 [256 * 320];
__device__ float g_W1 [256 * 256];
__device__ float g_W2 [256 * 256];
__device__ float g_Wao[256 * 256];
__device__ float g_Bao[256];
__device__ float g_Wbtr[4096 * 256];
__device__ float g_Wbti[4096 * 256];
__device__ float g_Wctr[6400 * 256];
__device__ float g_Wcti[6400 * 256];
__device__ float g_Wdtw[1600 * 256];
__device__ float g_x1[BATCH * LATENT];
__device__ float g_x2[BATCH * LATENT];
__device__ float g_hz[BATCH * LATENT];
__device__ float g_ao[BATCH * LATENT];
__device__ float g_zincr_r[BATCH * CD];
__device__ float g_zincr_i[BATCH * CD];
__device__ float g_ytr[BATCH * NY];
__device__ float g_yti[BATCH * NY];
__device__ float g_ytd[BATCH * NY];

// ---------------- PTX helpers ----------------
__device__ __forceinline__ uint32_t f2tf32(float f) {
    uint32_t r;
    asm("cvt.rna.tf32.f32 %0, %1;" : "=r"(r) : "f"(f));
    return r;
}
__device__ __forceinline__ float rnd_tf32(float f) { return __uint_as_float(f2tf32(f)); }

__device__ __forceinline__ void ldsm4(uint32_t& a0, uint32_t& a1, uint32_t& a2, uint32_t& a3,
                                      uint32_t addr) {
    asm volatile("ldmatrix.sync.aligned.m8n8.x4.shared.b16 {%0,%1,%2,%3}, [%4];"
                 : "=r"(a0), "=r"(a1), "=r"(a2), "=r"(a3) : "r"(addr));
}
__device__ __forceinline__ void mma_tf32(float* c,
                                         uint32_t a0, uint32_t a1, uint32_t a2, uint32_t a3,
                                         uint32_t b0, uint32_t b1) {
    asm volatile(
        "mma.sync.aligned.m16n8k8.row.col.f32.tf32.tf32.f32 "
        "{%0,%1,%2,%3},{%4,%5,%6,%7},{%8,%9},{%0,%1,%2,%3};"
        : "+f"(c[0]), "+f"(c[1]), "+f"(c[2]), "+f"(c[3])
        : "r"(a0), "r"(a1), "r"(a2), "r"(a3), "r"(b0), "r"(b1));
}
__device__ __forceinline__ void cp16(uint32_t dst, const float* src, int sz) {
    asm volatile("cp.async.cg.shared.global [%0], [%1], 16, %2;"
                 :: "r"(dst), "l"(src), "r"(sz));
}

// ---------------- prep (identical numerics to R3/R6/R7) ----------------
#define E_A0  (BATCH * 320)
#define E_W0  (E_A0  + 256 * 320)
#define E_W1  (E_W0  + 65536)
#define E_W2  (E_W1  + 65536)
#define E_WAO (E_W2  + 65536)
#define E_BAO (E_WAO + 256)
#define E_BTR (E_BAO + 4096 * 256)
#define E_BTI (E_BTR + 4096 * 256)
#define E_CTR (E_BTI + 6400 * 256)
#define E_CTI (E_CTR + 6400 * 256)
#define E_DTW (E_CTI + 1600 * 256)

__global__ void prep_kernel(const float* __restrict__ zt, const float* __restrict__ dt,
                            const float* __restrict__ ut,
                            const float* __restrict__ sw0, const float* __restrict__ sw1,
                            const float* __restrict__ sw2,
                            const float* __restrict__ aw, const float* __restrict__ ab,
                            const float* __restrict__ ow, const float* __restrict__ ob,
                            const float* __restrict__ btr, const float* __restrict__ bti,
                            const float* __restrict__ ctr, const float* __restrict__ cti,
                            const float* __restrict__ dtw)
{
    for (int idx = blockIdx.x * blockDim.x + threadIdx.x; idx < E_DTW;
         idx += gridDim.x * blockDim.x) {
        if (idx < E_A0) {
            int m = idx / 320, c = idx % 320;
            float v = 0.f;
            if (c < 256)       v = zt[m * 256 + c];
            else if (c < 288)  v = ut[m * UDIM + (c - 256)];
            else if (c == 288) v = dt[m];
            g_A0[idx] = rnd_tf32(v);
        } else if (idx < E_W0) {
            int j = idx - E_A0;
            int r = j / 320, c = j % 320;
            g_W0[j] = (c < 289) ? rnd_tf32(sw0[r * 289 + c]) : 0.f;
        } else if (idx < E_W1) {
            int j = idx - E_W0;  g_W1[j] = rnd_tf32(sw1[j]);
        } else if (idx < E_W2) {
            int j = idx - E_W1;  g_W2[j] = rnd_tf32(sw2[j]);
        } else if (idx < E_WAO) {
            int j = idx - E_W2;
            g_Wao[j] = rnd_tf32((j < 128 * 256) ? aw[j] : ow[j - 128 * 256]);
        } else if (idx < E_BAO) {
            int j = idx - E_WAO;
            g_Bao[j] = (j < 128) ? ab[j] : ob[j - 128];
        } else if (idx < E_BTR) {
            int j = idx - E_BAO; g_Wbtr[j] = rnd_tf32(btr[j]);
        } else if (idx < E_BTI) {
            int j = idx - E_BTR; g_Wbti[j] = rnd_tf32(bti[j]);
        } else if (idx < E_CTR) {
            int j = idx - E_BTI; g_Wctr[j] = rnd_tf32(ctr[j]);
        } else if (idx < E_CTI) {
            int j = idx - E_CTR; g_Wcti[j] = rnd_tf32(cti[j]);
        } else {
            int j = idx - E_CTI; g_Wdtw[j] = rnd_tf32(dtw[j]);
        }
    }
}

// ---------------------------------------------------------------------------
// mma.sync tf32 fused GEMM, 256 threads, 2 CTAs/SM (phase decorrelation).
// CTA tile 128 x 128, BK=32, 3-stage cp.async, one sync per chunk.
// 8 warps as 2(m) x 4(n); warp tile 64 x 32 (mt=4, nt=4, acc 64 regs).
//   MODE 1: BN(eval)+ReLU, ROUND, ldc=256
//   MODE 2: +bias store, ldc=256
//   MODE 3: +bias, contract 32-col u-groups with ut*dt (4 groups/tile), ldc=128
//   MODE 4: +bias, contract the tile's 128 cols with zv (1 y/tile), ldc=NY
//   MODE 5: MODE 3 with group bounds (Dt), ldc=NY
// ---------------------------------------------------------------------------
template <int MODE, int ROUND>
__global__ __launch_bounds__(NTH, 2)
void gemm_tc(const float* __restrict__ A, int K,
             const float* __restrict__ W, int N,
             const float* __restrict__ bias,
             const float* __restrict__ p0,   // ut (3/5) | zv base (4)
             const float* __restrict__ p1,   // dt (3/5)
             const float* __restrict__ p2,   // bn gamma (1)
             const float* __restrict__ p3,   // bn beta  (1)
             float* __restrict__ C, int ldc)
{
    extern __shared__ float sm[];
    const uint32_t* smb = (const uint32_t*)sm;
    float* sbias = sm + CTRLF;
    float* sg    = sbias + 128;
    float* sbe   = sg + 128;
    float* red   = sbe + 128;           // 512 floats (MODE 4)

    const int tid  = threadIdx.x;
    const int lane = tid & 31;
    const int warp = tid >> 5;
    const int m0 = blockIdx.x * 128;
    const int n0 = blockIdx.y * 128;
    const int wm = warp >> 2;           // 0..1 (64 rows)
    const int wn = warp & 3;            // 0..3 (32 cols)
    const int gq = lane >> 2;
    const int tq = lane & 3;
    const uint32_t smu = (uint32_t)__cvta_generic_to_shared(sm);

    if (tid < 128) {
        int n = n0 + tid;
        sbias[tid] = (n < N) ? bias[n] : 0.f;
        if (MODE == 1) {
            sg[tid]  = p2[n] * rsqrtf(1.f + 1e-5f);
            sbe[tid] = p3[n];
        }
    }

    float acc[4][4][4];
#pragma unroll
    for (int i = 0; i < 4; i++)
#pragma unroll
        for (int j = 0; j < 4; j++)
#pragma unroll
            for (int r = 0; r < 4; r++) acc[i][j][r] = 0.f;

    const int row_off = lane & 15;
    const int hi = lane >> 4;
    uint32_t abyte[4]; int arx[4];
#pragma unroll
    for (int mt = 0; mt < 4; mt++) {
        int r = wm * 64 + mt * 16 + row_off;
        abyte[mt] = smu + (uint32_t)(r * 128);
        arx[mt] = r & 7;
    }
    int bidx[4], bx[4];
#pragma unroll
    for (int nt = 0; nt < 4; nt++) {
        int n = wn * 32 + nt * 8 + gq;
        bidx[nt] = n * 32 + tq;
        bx[nt] = n & 7;
    }

    auto issue = [&](int kc, int s) {
#pragma unroll
        for (int i = 0; i < 8; i++) {
            int idx = tid + i * 256;            // 0..2047
            int r = idx >> 3, k4 = idx & 7;
            uint32_t dst; const float* src; int sz = 16;
            if (r < 128) {
                dst = smu + (uint32_t)((s * STG + r * 32 + ((k4 ^ (r & 7)) << 2)) * 4);
                src = A + (size_t)(m0 + r) * K + kc * 32 + k4 * 4;
            } else {
                int rb = r - 128;
                dst = smu + (uint32_t)((s * STG + 4096 + rb * 32 + ((k4 ^ (rb & 7)) << 2)) * 4);
                int n = n0 + rb;
                if (n < N) src = W + (size_t)n * K + kc * 32 + k4 * 4;
                else { src = W; sz = 0; }
            }
            cp16(dst, src, sz);
        }
        asm volatile("cp.async.commit_group;" ::: "memory");
    };

    auto compute = [&](int s) {
        const uint32_t sa = (uint32_t)(s * STG * 4);
        const int sbf = s * STG + 4096;
#pragma unroll
        for (int ks = 0; ks < 4; ks++) {
            uint32_t bf0[4], bf1[4];
#pragma unroll
            for (int nt = 0; nt < 4; nt++) {
                bf0[nt] = smb[sbf + bidx[nt] + (((2 * ks)     ^ bx[nt]) << 2)];
                bf1[nt] = smb[sbf + bidx[nt] + (((2 * ks + 1) ^ bx[nt]) << 2)];
            }
            const int k4a = 2 * ks + hi;
#pragma unroll
            for (int mt = 0; mt < 4; mt++) {
                uint32_t a0, a1, a2, a3;
                ldsm4(a0, a1, a2, a3, abyte[mt] + sa + (uint32_t)((k4a ^ arx[mt]) << 4));
#pragma unroll
                for (int nt = 0; nt < 4; nt++)
                    mma_tf32(acc[mt][nt], a0, a1, a2, a3, bf0[nt], bf1[nt]);
            }
        }
    };

    const int NC = K >> 5;
    issue(0, 0);
    issue(1, 1);
    for (int kc = 0; kc < NC; kc++) {
        asm volatile("cp.async.wait_group 1;" ::: "memory");
        __syncthreads();
        int pf = kc + 2;
        if (pf < NC) issue(pf, pf % 3);
        else asm volatile("cp.async.commit_group;" ::: "memory");
        compute(kc % 3);
    }

    // ---------------- epilogues ----------------
    // acc r=h*2+p -> m = m0+wm*64+mt*16+gq+h*8 ; tile col nl = wn*32+nt*8+tq*2+p
    if (MODE <= 2) {
#pragma unroll
        for (int nt = 0; nt < 4; nt++)
#pragma unroll
            for (int p = 0; p < 2; p++) {
                int nl = wn * 32 + nt * 8 + tq * 2 + p;
                int n = n0 + nl;
                float bi = sbias[nl];
                float gg = (MODE == 1) ? sg[nl] : 0.f;
                float bb = (MODE == 1) ? sbe[nl] : 0.f;
#pragma unroll
                for (int mt = 0; mt < 4; mt++)
#pragma unroll
                    for (int h = 0; h < 2; h++) {
                        int m = m0 + wm * 64 + mt * 16 + gq + h * 8;
                        float v = acc[mt][nt][h * 2 + p] + bi;
                        if (MODE == 1) v = fmaxf(v * gg + bb, 0.f);
                        C[(size_t)m * ldc + n] = ROUND ? rnd_tf32(v) : v;
                    }
            }
    } else if (MODE == 3 || MODE == 5) {
        // warp's 32 cols = exactly one u-group; in-warp contraction
        const int gcol = blockIdx.y * 4 + wn;
        const bool gvalid = (MODE == 3) || (gcol < NY);
#pragma unroll
        for (int mt = 0; mt < 4; mt++)
#pragma unroll
            for (int h = 0; h < 2; h++) {
                int m = m0 + wm * 64 + mt * 16 + gq + h * 8;
                float s = 0.f;
#pragma unroll
                for (int nt = 0; nt < 4; nt++)
#pragma unroll
                    for (int p = 0; p < 2; p++) {
                        int u = nt * 8 + tq * 2 + p;
                        s += (acc[mt][nt][h * 2 + p] + sbias[wn * 32 + u])
                             * p0[(size_t)m * UDIM + u];
                    }
                s += __shfl_xor_sync(0xffffffffu, s, 1);
                s += __shfl_xor_sync(0xffffffffu, s, 2);
                if (tq == 0 && gvalid)
                    C[(size_t)m * ldc + gcol] = s * p1[m];
            }
    } else {  // MODE 4: whole 128-col tile = one y; contract with zv
#pragma unroll
        for (int mt = 0; mt < 4; mt++)
#pragma unroll
            for (int h = 0; h < 2; h++) {
                int rl = wm * 64 + mt * 16 + gq + h * 8;
                int m = m0 + rl;
                float s = 0.f;
#pragma unroll
                for (int nt = 0; nt < 4; nt++)
#pragma unroll
                    for (int p = 0; p < 2; p++) {
                        int cl = wn * 32 + nt * 8 + tq * 2 + p;
                        s += (acc[mt][nt][h * 2 + p] + sbias[cl])
                             * p0[(size_t)m * 256 + cl];
                    }
                s += __shfl_xor_sync(0xffffffffu, s, 1);
                s += __shfl_xor_sync(0xffffffffu, s, 2);
                if (tq == 0)
                    red[rl * 4 + wn] = s;
            }
        __syncthreads();
        if (tid < 128) {
            float s = red[tid * 4] + red[tid * 4 + 1]
                    + red[tid * 4 + 2] + red[tid * 4 + 3];
            C[(size_t)(m0 + tid) * ldc + blockIdx.y] = s;
        }
    }
}

// z_next = exp(-softplus(a) + i*omega) * z + zincr
__global__ void znext_kernel(const float* __restrict__ zt, float* __restrict__ out)
{
    int idx = blockIdx.x * blockDim.x + threadIdx.x;
    if (idx >= BATCH * CD) return;
    int m = idx >> 7, c = idx & 127;
    float a = g_ao[m * 256 + c];
    float w = g_ao[m * 256 + 128 + c];
    float ea = 1.f / (1.f + expf(a));
    float lr = ea * cosf(w);
    float li = ea * sinf(w);
    float zr = zt[m * 256 + c];
    float zi = zt[m * 256 + 128 + c];
    out[m * 256 + c]       = lr * zr - li * zi + g_zincr_r[idx];
    out[m * 256 + 128 + c] = lr * zi + li * zr + g_zincr_i[idx];
}

__global__ void yt_combine_kernel(float* __restrict__ out)
{
    int idx = blockIdx.x * blockDim.x + threadIdx.x;
    if (idx >= BATCH * NY) return;
    out[BATCH * LATENT + idx] = g_ytr[idx] - g_yti[idx] + g_ytd[idx];
}

// ================================================================================
extern "C" void kernel_launch(void* const* d_in, const int* in_sizes, int n_in,
                              void* d_out, int out_size)
{
    const float* zt      = (const float*)d_in[0];
    const float* dt      = (const float*)d_in[1];
    const float* ut      = (const float*)d_in[2];
    const float* sel_w0  = (const float*)d_in[3];
    const float* sel_b0  = (const float*)d_in[4];
    const float* sel_g0  = (const float*)d_in[5];
    const float* sel_be0 = (const float*)d_in[6];
    const float* sel_w1  = (const float*)d_in[7];
    const float* sel_b1  = (const float*)d_in[8];
    const float* sel_g1  = (const float*)d_in[9];
    const float* sel_be1 = (const float*)d_in[10];
    const float* sel_w2  = (const float*)d_in[11];
    const float* sel_b2  = (const float*)d_in[12];
    const float* alpha_w = (const float*)d_in[13];
    const float* alpha_b = (const float*)d_in[14];
    const float* omega_w = (const float*)d_in[15];
    const float* omega_b = (const float*)d_in[16];
    const float* btr_w   = (const float*)d_in[17];
    const float* btr_b   = (const float*)d_in[18];
    const float* bti_w   = (const float*)d_in[19];
    const float* bti_b   = (const float*)d_in[20];
    const float* ctr_w   = (const float*)d_in[21];
    const float* ctr_b   = (const float*)d_in[22];
    const float* cti_w   = (const float*)d_in[23];
    const float* cti_b   = (const float*)d_in[24];
    const float* dtw_w   = (const float*)d_in[25];
    const float* dtw_b   = (const float*)d_in[26];
    float* out = (float*)d_out;

    float *A0, *W0, *W1, *W2, *Wao, *Bao, *Wbtr, *Wbti, *Wctr, *Wcti, *Wdtw;
    float *x1, *x2, *hz, *ao, *zir, *zii, *ytr, *yti, *ytd;
    cudaGetSymbolAddress((void**)&A0,   g_A0);
    cudaGetSymbolAddress((void**)&W0,   g_W0);
    cudaGetSymbolAddress((void**)&W1,   g_W1);
    cudaGetSymbolAddress((void**)&W2,   g_W2);
    cudaGetSymbolAddress((void**)&Wao,  g_Wao);
    cudaGetSymbolAddress((void**)&Bao,  g_Bao);
    cudaGetSymbolAddress((void**)&Wbtr, g_Wbtr);
    cudaGetSymbolAddress((void**)&Wbti, g_Wbti);
    cudaGetSymbolAddress((void**)&Wctr, g_Wctr);
    cudaGetSymbolAddress((void**)&Wcti, g_Wcti);
    cudaGetSymbolAddress((void**)&Wdtw, g_Wdtw);
    cudaGetSymbolAddress((void**)&x1,  g_x1);
    cudaGetSymbolAddress((void**)&x2,  g_x2);
    cudaGetSymbolAddress((void**)&hz,  g_hz);
    cudaGetSymbolAddress((void**)&ao,  g_ao);
    cudaGetSymbolAddress((void**)&zir, g_zincr_r);
    cudaGetSymbolAddress((void**)&zii, g_zincr_i);
    cudaGetSymbolAddress((void**)&ytr, g_ytr);
    cudaGetSymbolAddress((void**)&yti, g_yti);
    cudaGetSymbolAddress((void**)&ytd, g_ytd);

    cudaFuncSetAttribute((const void*)gemm_tc<1,1>, cudaFuncAttributeMaxDynamicSharedMemorySize, SMEM_BYTES);
    cudaFuncSetAttribute((const void*)gemm_tc<2,1>, cudaFuncAttributeMaxDynamicSharedMemorySize, SMEM_BYTES);
    cudaFuncSetAttribute((const void*)gemm_tc<2,0>, cudaFuncAttributeMaxDynamicSharedMemorySize, SMEM_BYTES);
    cudaFuncSetAttribute((const void*)gemm_tc<3,0>, cudaFuncAttributeMaxDynamicSharedMemorySize, SMEM_BYTES);
    cudaFuncSetAttribute((const void*)gemm_tc<4,0>, cudaFuncAttributeMaxDynamicSharedMemorySize, SMEM_BYTES);
    cudaFuncSetAttribute((const void*)gemm_tc<5,0>, cudaFuncAttributeMaxDynamicSharedMemorySize, SMEM_BYTES);

    dim3 thr(NTH);

    prep_kernel<<<2048, 256>>>(zt, dt, ut, sel_w0, sel_w1, sel_w2,
                               alpha_w, alpha_b, omega_w, omega_b,
                               btr_w, bti_w, ctr_w, cti_w, dtw_w);

    // selector MLP
    gemm_tc<1,1><<<dim3(64, 2), thr, SMEM_BYTES>>>(A0, 320, W0, 256, sel_b0,
                                                   nullptr, nullptr, sel_g0, sel_be0, x1, 256);
    gemm_tc<1,1><<<dim3(64, 2), thr, SMEM_BYTES>>>(x1, 256, W1, 256, sel_b1,
                                                   nullptr, nullptr, sel_g1, sel_be1, x2, 256);
    gemm_tc<2,1><<<dim3(64, 2), thr, SMEM_BYTES>>>(x2, 256, W2, 256, sel_b2,
                                                   nullptr, nullptr, nullptr, nullptr, hz, 256);
    gemm_tc<2,0><<<dim3(64, 2), thr, SMEM_BYTES>>>(hz, 256, Wao, 256, Bao,
                                                   nullptr, nullptr, nullptr, nullptr, ao, 256);
    // Bt (real, imag) fused with einsum('bcu,bu->bc')
    gemm_tc<3,0><<<dim3(64, 32), thr, SMEM_BYTES>>>(hz, 256, Wbtr, 4096, btr_b,
                                                    ut, dt, nullptr, nullptr, zir, CD);
    gemm_tc<3,0><<<dim3(64, 32), thr, SMEM_BYTES>>>(hz, 256, Wbti, 4096, bti_b,
                                                    ut, dt, nullptr, nullptr, zii, CD);
    znext_kernel<<<(BATCH * CD) / 256, 256>>>(zt, out);
    // Ct (real, imag) fused with einsum('byc,bc->by')
    gemm_tc<4,0><<<dim3(64, 50), thr, SMEM_BYTES>>>(hz, 256, Wctr, 6400, ctr_b,
                                                    out, nullptr, nullptr, nullptr, ytr, NY);
    gemm_tc<4,0><<<dim3(64, 50), thr, SMEM_BYTES>>>(hz, 256, Wcti, 6400, cti_b,
                                                    out + 128, nullptr, nullptr, nullptr, yti, NY);
    // Dt fused with einsum('byu,bu->by')
    gemm_tc<5,0><<<dim3(64, 13), thr, SMEM_BYTES>>>(hz, 256, Wdtw, 1600, dtw_b,
                                                    ut, dt, nullptr, nullptr, ytd, NY);
    yt_combine_kernel<<<(BATCH * NY + 255) / 256, 256>>>(out);
}

// round 9
// speedup vs baseline: 7.9284x; 1.4660x over previous
#include <cuda_runtime.h>
#include <cuda_fp16.h>
#include <math.h>
#include <stdint.h>

#define BATCH  8192
#define LATENT 256
#define CD     128
#define UDIM   32
#define NY     50
#define NTH    256
#define STGW   8192                       // 32-bit words per stage (32 KB)
#define CTRLW  (3 * STGW)
#define SMEM_BYTES ((CTRLW + 1024) * 4)   // + bias/g/be/red

// ---------------- scratch (static device globals; no allocation) ----------------
__device__ __half g_A0 [BATCH * 320];
__device__ __half g_W0 [256 * 320];
__device__ __half g_W1 [256 * 256];
__device__ __half g_W2 [256 * 256];
__device__ __half g_Wao[256 * 256];
__device__ float  g_Bao[256];
__device__ __half g_Wbtr[4096 * 256];
__device__ __half g_Wbti[4096 * 256];
__device__ __half g_Wctr[6400 * 256];
__device__ __half g_Wcti[6400 * 256];
__device__ __half g_Wdtw[1600 * 256];
__device__ __half g_x1[BATCH * LATENT];
__device__ __half g_x2[BATCH * LATENT];
__device__ __half g_hz[BATCH * LATENT];
__device__ float g_ao[BATCH * LATENT];
__device__ float g_zincr_r[BATCH * CD];
__device__ float g_zincr_i[BATCH * CD];
__device__ float g_ytr[BATCH * NY];
__device__ float g_yti[BATCH * NY];
__device__ float g_ytd[BATCH * NY];

// ---------------- PTX helpers ----------------
__device__ __forceinline__ void ldsm4(uint32_t& a0, uint32_t& a1, uint32_t& a2, uint32_t& a3,
                                      uint32_t addr) {
    asm volatile("ldmatrix.sync.aligned.m8n8.x4.shared.b16 {%0,%1,%2,%3}, [%4];"
                 : "=r"(a0), "=r"(a1), "=r"(a2), "=r"(a3) : "r"(addr));
}
__device__ __forceinline__ void mma_f16(float* c,
                                        uint32_t a0, uint32_t a1, uint32_t a2, uint32_t a3,
                                        uint32_t b0, uint32_t b1) {
    asm volatile(
        "mma.sync.aligned.m16n8k16.row.col.f32.f16.f16.f32 "
        "{%0,%1,%2,%3},{%4,%5,%6,%7},{%8,%9},{%0,%1,%2,%3};"
        : "+f"(c[0]), "+f"(c[1]), "+f"(c[2]), "+f"(c[3])
        : "r"(a0), "r"(a1), "r"(a2), "r"(a3), "r"(b0), "r"(b1));
}
__device__ __forceinline__ void cp16(uint32_t dst, const void* src, int sz) {
    asm volatile("cp.async.cg.shared.global [%0], [%1], 16, %2;"
                 :: "r"(dst), "l"(src), "r"(sz));
}

// ---------------- prep: convert all GEMM operands to fp16 ----------------
#define E_A0  (BATCH * 320)
#define E_W0  (E_A0  + 256 * 320)
#define E_W1  (E_W0  + 65536)
#define E_W2  (E_W1  + 65536)
#define E_WAO (E_W2  + 65536)
#define E_BAO (E_WAO + 256)
#define E_BTR (E_BAO + 4096 * 256)
#define E_BTI (E_BTR + 4096 * 256)
#define E_CTR (E_BTI + 6400 * 256)
#define E_CTI (E_CTR + 6400 * 256)
#define E_DTW (E_CTI + 1600 * 256)

__global__ void prep_kernel(const float* __restrict__ zt, const float* __restrict__ dt,
                            const float* __restrict__ ut,
                            const float* __restrict__ sw0, const float* __restrict__ sw1,
                            const float* __restrict__ sw2,
                            const float* __restrict__ aw, const float* __restrict__ ab,
                            const float* __restrict__ ow, const float* __restrict__ ob,
                            const float* __restrict__ btr, const float* __restrict__ bti,
                            const float* __restrict__ ctr, const float* __restrict__ cti,
                            const float* __restrict__ dtw)
{
    for (int idx = blockIdx.x * blockDim.x + threadIdx.x; idx < E_DTW;
         idx += gridDim.x * blockDim.x) {
        if (idx < E_A0) {
            int m = idx / 320, c = idx % 320;
            float v = 0.f;
            if (c < 256)       v = zt[m * 256 + c];
            else if (c < 288)  v = ut[m * UDIM + (c - 256)];
            else if (c == 288) v = dt[m];
            g_A0[idx] = __float2half(v);
        } else if (idx < E_W0) {
            int j = idx - E_A0;
            int r = j / 320, c = j % 320;
            g_W0[j] = __float2half((c < 289) ? sw0[r * 289 + c] : 0.f);
        } else if (idx < E_W1) {
            int j = idx - E_W0;  g_W1[j] = __float2half(sw1[j]);
        } else if (idx < E_W2) {
            int j = idx - E_W1;  g_W2[j] = __float2half(sw2[j]);
        } else if (idx < E_WAO) {
            int j = idx - E_W2;
            g_Wao[j] = __float2half((j < 128 * 256) ? aw[j] : ow[j - 128 * 256]);
        } else if (idx < E_BAO) {
            int j = idx - E_WAO;
            g_Bao[j] = (j < 128) ? ab[j] : ob[j - 128];
        } else if (idx < E_BTR) {
            int j = idx - E_BAO; g_Wbtr[j] = __float2half(btr[j]);
        } else if (idx < E_BTI) {
            int j = idx - E_BTR; g_Wbti[j] = __float2half(bti[j]);
        } else if (idx < E_CTR) {
            int j = idx - E_BTI; g_Wctr[j] = __float2half(ctr[j]);
        } else if (idx < E_CTI) {
            int j = idx - E_CTR; g_Wcti[j] = __float2half(cti[j]);
        } else {
            int j = idx - E_CTI; g_Wdtw[j] = __float2half(dtw[j]);
        }
    }
}

// ---------------------------------------------------------------------------
// fp16 m16n8k16 fused GEMM, 256 threads, 2 CTAs/SM target.
// CTA tile 128 x 128, BK=64 (128B fp16 rows), 3-stage cp.async, 1 sync/chunk.
// 8 warps as 2(m) x 4(n); warp tile 64 x 32 (mt=4, nt=4, acc 64 regs).
//   MODE 1: BN(eval)+ReLU -> half out, ldc=256
//   MODE 2: +bias -> half out (OUTH=1) or float out (OUTH=0), ldc=256
//   MODE 3: +bias, contract 32-col u-group/warp with ut*dt, ldc=128
//   MODE 4: +bias, contract tile's 128 cols with zv (1 y/tile), ldc=NY
//   MODE 5: MODE 3 with group bounds (Dt), ldc=NY
// ---------------------------------------------------------------------------
template <int MODE, int OUTH>
__global__ __launch_bounds__(NTH, 2)
void gemm_hc(const __half* __restrict__ A, int K,
             const __half* __restrict__ W, int N,
             const float* __restrict__ bias,
             const float* __restrict__ p0,   // ut (3/5) | zv base (4)
             const float* __restrict__ p1,   // dt (3/5)
             const float* __restrict__ p2,   // bn gamma (1)
             const float* __restrict__ p3,   // bn beta  (1)
             void* __restrict__ Cout, int ldc)
{
    extern __shared__ float sm[];
    const uint32_t* smb = (const uint32_t*)sm;
    float* sbias = sm + CTRLW;
    float* sg    = sbias + 128;
    float* sbe   = sg + 128;
    float* red   = sbe + 128;           // 512 floats (MODE 4)

    const int tid  = threadIdx.x;
    const int lane = tid & 31;
    const int warp = tid >> 5;
    const int m0 = blockIdx.x * 128;
    const int n0 = blockIdx.y * 128;
    const int wm = warp >> 2;           // 0..1 (64 rows)
    const int wn = warp & 3;            // 0..3 (32 cols)
    const int gq = lane >> 2;
    const int tq = lane & 3;
    const uint32_t smu = (uint32_t)__cvta_generic_to_shared(sm);

    if (tid < 128) {
        int n = n0 + tid;
        sbias[tid] = (n < N) ? bias[n] : 0.f;
        if (MODE == 1) {
            sg[tid]  = p2[n] * rsqrtf(1.f + 1e-5f);
            sbe[tid] = p3[n];
        }
    }

    float acc[4][4][4];
#pragma unroll
    for (int i = 0; i < 4; i++)
#pragma unroll
        for (int j = 0; j < 4; j++)
#pragma unroll
            for (int r = 0; r < 4; r++) acc[i][j][r] = 0.f;

    // ldmatrix lane constants (fp16 m16n8k16: 16B granule = 8 halves = k8)
    const int row_off = lane & 15;
    const int hi = lane >> 4;
    uint32_t abyte[4]; int arx[4];
#pragma unroll
    for (int mt = 0; mt < 4; mt++) {
        int r = wm * 64 + mt * 16 + row_off;
        abyte[mt] = smu + (uint32_t)(r * 128);
        arx[mt] = r & 7;
    }
    int bidx[4], bx[4];
#pragma unroll
    for (int nt = 0; nt < 4; nt++) {
        int n = wn * 32 + nt * 8 + gq;
        bidx[nt] = n * 32 + tq;         // 32 words per 128B row
        bx[nt] = n & 7;
    }

    auto issue = [&](int kc, int s) {
#pragma unroll
        for (int i = 0; i < 8; i++) {
            int idx = tid + i * 256;            // 0..2047
            int r = idx >> 3, g16 = idx & 7;    // row, 16B granule (8 halves)
            uint32_t dst; const __half* src; int sz = 16;
            if (r < 128) {
                dst = smu + (uint32_t)(s * 32768 + r * 128 + ((g16 ^ (r & 7)) << 4));
                src = A + (size_t)(m0 + r) * K + kc * 64 + g16 * 8;
            } else {
                int rb = r - 128;
                dst = smu + (uint32_t)(s * 32768 + 16384 + rb * 128 + ((g16 ^ (rb & 7)) << 4));
                int n = n0 + rb;
                if (n < N) src = W + (size_t)n * K + kc * 64 + g16 * 8;
                else { src = W; sz = 0; }
            }
            cp16(dst, src, sz);
        }
        asm volatile("cp.async.commit_group;" ::: "memory");
    };

    auto compute = [&](int s) {
        const uint32_t sa = (uint32_t)(s * 32768);
        const int sbf = s * STGW + 4096;        // B region word offset
#pragma unroll
        for (int ks = 0; ks < 4; ks++) {        // 4 x k16 per 64-k chunk
            uint32_t bf0[4], bf1[4];
#pragma unroll
            for (int nt = 0; nt < 4; nt++) {
                bf0[nt] = smb[sbf + bidx[nt] + (((2 * ks)     ^ bx[nt]) << 2)];
                bf1[nt] = smb[sbf + bidx[nt] + (((2 * ks + 1) ^ bx[nt]) << 2)];
            }
            const int ga = 2 * ks + hi;
#pragma unroll
            for (int mt = 0; mt < 4; mt++) {
                uint32_t a0, a1, a2, a3;
                ldsm4(a0, a1, a2, a3, abyte[mt] + sa + (uint32_t)((ga ^ arx[mt]) << 4));
#pragma unroll
                for (int nt = 0; nt < 4; nt++)
                    mma_f16(acc[mt][nt], a0, a1, a2, a3, bf0[nt], bf1[nt]);
            }
        }
    };

    const int NC = K >> 6;                      // 64 k per chunk
    issue(0, 0);
    issue(1, 1);
    for (int kc = 0; kc < NC; kc++) {
        asm volatile("cp.async.wait_group 1;" ::: "memory");
        __syncthreads();
        int pf = kc + 2;
        if (pf < NC) issue(pf, pf % 3);
        else asm volatile("cp.async.commit_group;" ::: "memory");
        compute(kc % 3);
    }

    // ---------------- epilogues ----------------
    // acc r=h*2+p -> m = m0+wm*64+mt*16+gq+h*8 ; tile col nl = wn*32+nt*8+tq*2+p
    if (MODE <= 2) {
#pragma unroll
        for (int nt = 0; nt < 4; nt++)
#pragma unroll
            for (int p = 0; p < 2; p++) {
                int nl = wn * 32 + nt * 8 + tq * 2 + p;
                int n = n0 + nl;
                float bi = sbias[nl];
                float gg = (MODE == 1) ? sg[nl] : 0.f;
                float bb = (MODE == 1) ? sbe[nl] : 0.f;
#pragma unroll
                for (int mt = 0; mt < 4; mt++)
#pragma unroll
                    for (int h = 0; h < 2; h++) {
                        int m = m0 + wm * 64 + mt * 16 + gq + h * 8;
                        float v = acc[mt][nt][h * 2 + p] + bi;
                        if (MODE == 1) v = fmaxf(v * gg + bb, 0.f);
                        if (OUTH) ((__half*)Cout)[(size_t)m * ldc + n] = __float2half(v);
                        else      ((float*)Cout)[(size_t)m * ldc + n] = v;
                    }
            }
    } else if (MODE == 3 || MODE == 5) {
        const int gcol = blockIdx.y * 4 + wn;
        const bool gvalid = (MODE == 3) || (gcol < NY);
        float* Cf = (float*)Cout;
#pragma unroll
        for (int mt = 0; mt < 4; mt++)
#pragma unroll
            for (int h = 0; h < 2; h++) {
                int m = m0 + wm * 64 + mt * 16 + gq + h * 8;
                float s = 0.f;
#pragma unroll
                for (int nt = 0; nt < 4; nt++)
#pragma unroll
                    for (int p = 0; p < 2; p++) {
                        int u = nt * 8 + tq * 2 + p;
                        s += (acc[mt][nt][h * 2 + p] + sbias[wn * 32 + u])
                             * p0[(size_t)m * UDIM + u];
                    }
                s += __shfl_xor_sync(0xffffffffu, s, 1);
                s += __shfl_xor_sync(0xffffffffu, s, 2);
                if (tq == 0 && gvalid)
                    Cf[(size_t)m * ldc + gcol] = s * p1[m];
            }
    } else {  // MODE 4: whole 128-col tile = one y; contract with zv
        float* Cf = (float*)Cout;
#pragma unroll
        for (int mt = 0; mt < 4; mt++)
#pragma unroll
            for (int h = 0; h < 2; h++) {
                int rl = wm * 64 + mt * 16 + gq + h * 8;
                int m = m0 + rl;
                float s = 0.f;
#pragma unroll
                for (int nt = 0; nt < 4; nt++)
#pragma unroll
                    for (int p = 0; p < 2; p++) {
                        int cl = wn * 32 + nt * 8 + tq * 2 + p;
                        s += (acc[mt][nt][h * 2 + p] + sbias[cl])
                             * p0[(size_t)m * 256 + cl];
                    }
                s += __shfl_xor_sync(0xffffffffu, s, 1);
                s += __shfl_xor_sync(0xffffffffu, s, 2);
                if (tq == 0)
                    red[rl * 4 + wn] = s;
            }
        __syncthreads();
        if (tid < 128) {
            float s = red[tid * 4] + red[tid * 4 + 1]
                    + red[tid * 4 + 2] + red[tid * 4 + 3];
            Cf[(size_t)(m0 + tid) * ldc + blockIdx.y] = s;
        }
    }
}

// z_next = exp(-softplus(a) + i*omega) * z + zincr
__global__ void znext_kernel(const float* __restrict__ zt, float* __restrict__ out)
{
    int idx = blockIdx.x * blockDim.x + threadIdx.x;
    if (idx >= BATCH * CD) return;
    int m = idx >> 7, c = idx & 127;
    float a = g_ao[m * 256 + c];
    float w = g_ao[m * 256 + 128 + c];
    float ea = 1.f / (1.f + expf(a));
    float lr = ea * cosf(w);
    float li = ea * sinf(w);
    float zr = zt[m * 256 + c];
    float zi = zt[m * 256 + 128 + c];
    out[m * 256 + c]       = lr * zr - li * zi + g_zincr_r[idx];
    out[m * 256 + 128 + c] = lr * zi + li * zr + g_zincr_i[idx];
}

__global__ void yt_combine_kernel(float* __restrict__ out)
{
    int idx = blockIdx.x * blockDim.x + threadIdx.x;
    if (idx >= BATCH * NY) return;
    out[BATCH * LATENT + idx] = g_ytr[idx] - g_yti[idx] + g_ytd[idx];
}

// ================================================================================
extern "C" void kernel_launch(void* const* d_in, const int* in_sizes, int n_in,
                              void* d_out, int out_size)
{
    const float* zt      = (const float*)d_in[0];
    const float* dt      = (const float*)d_in[1];
    const float* ut      = (const float*)d_in[2];
    const float* sel_w0  = (const float*)d_in[3];
    const float* sel_b0  = (const float*)d_in[4];
    const float* sel_g0  = (const float*)d_in[5];
    const float* sel_be0 = (const float*)d_in[6];
    const float* sel_w1  = (const float*)d_in[7];
    const float* sel_b1  = (const float*)d_in[8];
    const float* sel_g1  = (const float*)d_in[9];
    const float* sel_be1 = (const float*)d_in[10];
    const float* sel_w2  = (const float*)d_in[11];
    const float* sel_b2  = (const float*)d_in[12];
    const float* alpha_w = (const float*)d_in[13];
    const float* alpha_b = (const float*)d_in[14];
    const float* omega_w = (const float*)d_in[15];
    const float* omega_b = (const float*)d_in[16];
    const float* btr_w   = (const float*)d_in[17];
    const float* btr_b   = (const float*)d_in[18];
    const float* bti_w   = (const float*)d_in[19];
    const float* bti_b   = (const float*)d_in[20];
    const float* ctr_w   = (const float*)d_in[21];
    const float* ctr_b   = (const float*)d_in[22];
    const float* cti_w   = (const float*)d_in[23];
    const float* cti_b   = (const float*)d_in[24];
    const float* dtw_w   = (const float*)d_in[25];
    const float* dtw_b   = (const float*)d_in[26];
    float* out = (float*)d_out;

    __half *A0, *W0, *W1, *W2, *Wao, *Wbtr, *Wbti, *Wctr, *Wcti, *Wdtw;
    __half *x1, *x2, *hz;
    float *Bao, *ao, *zir, *zii, *ytr, *yti, *ytd;
    cudaGetSymbolAddress((void**)&A0,   g_A0);
    cudaGetSymbolAddress((void**)&W0,   g_W0);
    cudaGetSymbolAddress((void**)&W1,   g_W1);
    cudaGetSymbolAddress((void**)&W2,   g_W2);
    cudaGetSymbolAddress((void**)&Wao,  g_Wao);
    cudaGetSymbolAddress((void**)&Bao,  g_Bao);
    cudaGetSymbolAddress((void**)&Wbtr, g_Wbtr);
    cudaGetSymbolAddress((void**)&Wbti, g_Wbti);
    cudaGetSymbolAddress((void**)&Wctr, g_Wctr);
    cudaGetSymbolAddress((void**)&Wcti, g_Wcti);
    cudaGetSymbolAddress((void**)&Wdtw, g_Wdtw);
    cudaGetSymbolAddress((void**)&x1,  g_x1);
    cudaGetSymbolAddress((void**)&x2,  g_x2);
    cudaGetSymbolAddress((void**)&hz,  g_hz);
    cudaGetSymbolAddress((void**)&ao,  g_ao);
    cudaGetSymbolAddress((void**)&zir, g_zincr_r);
    cudaGetSymbolAddress((void**)&zii, g_zincr_i);
    cudaGetSymbolAddress((void**)&ytr, g_ytr);
    cudaGetSymbolAddress((void**)&yti, g_yti);
    cudaGetSymbolAddress((void**)&ytd, g_ytd);

    cudaFuncSetAttribute((const void*)gemm_hc<1,1>, cudaFuncAttributeMaxDynamicSharedMemorySize, SMEM_BYTES);
    cudaFuncSetAttribute((const void*)gemm_hc<2,1>, cudaFuncAttributeMaxDynamicSharedMemorySize, SMEM_BYTES);
    cudaFuncSetAttribute((const void*)gemm_hc<2,0>, cudaFuncAttributeMaxDynamicSharedMemorySize, SMEM_BYTES);
    cudaFuncSetAttribute((const void*)gemm_hc<3,0>, cudaFuncAttributeMaxDynamicSharedMemorySize, SMEM_BYTES);
    cudaFuncSetAttribute((const void*)gemm_hc<4,0>, cudaFuncAttributeMaxDynamicSharedMemorySize, SMEM_BYTES);
    cudaFuncSetAttribute((const void*)gemm_hc<5,0>, cudaFuncAttributeMaxDynamicSharedMemorySize, SMEM_BYTES);

    dim3 thr(NTH);

    prep_kernel<<<2048, 256>>>(zt, dt, ut, sel_w0, sel_w1, sel_w2,
                               alpha_w, alpha_b, omega_w, omega_b,
                               btr_w, bti_w, ctr_w, cti_w, dtw_w);

    // selector MLP (half in/out)
    gemm_hc<1,1><<<dim3(64, 2), thr, SMEM_BYTES>>>(A0, 320, W0, 256, sel_b0,
                                                   nullptr, nullptr, sel_g0, sel_be0, x1, 256);
    gemm_hc<1,1><<<dim3(64, 2), thr, SMEM_BYTES>>>(x1, 256, W1, 256, sel_b1,
                                                   nullptr, nullptr, sel_g1, sel_be1, x2, 256);
    gemm_hc<2,1><<<dim3(64, 2), thr, SMEM_BYTES>>>(x2, 256, W2, 256, sel_b2,
                                                   nullptr, nullptr, nullptr, nullptr, hz, 256);
    // alpha|omega (float out for znext)
    gemm_hc<2,0><<<dim3(64, 2), thr, SMEM_BYTES>>>(hz, 256, Wao, 256, Bao,
                                                   nullptr, nullptr, nullptr, nullptr, ao, 256);
    // Bt (real, imag) fused with einsum('bcu,bu->bc')
    gemm_hc<3,0><<<dim3(64, 32), thr, SMEM_BYTES>>>(hz, 256, Wbtr, 4096, btr_b,
                                                    ut, dt, nullptr, nullptr, zir, CD);
    gemm_hc<3,0><<<dim3(64, 32), thr, SMEM_BYTES>>>(hz, 256, Wbti, 4096, bti_b,
                                                    ut, dt, nullptr, nullptr, zii, CD);
    znext_kernel<<<(BATCH * CD) / 256, 256>>>(zt, out);
    // Ct (real, imag) fused with einsum('byc,bc->by')
    gemm_hc<4,0><<<dim3(64, 50), thr, SMEM_BYTES>>>(hz, 256, Wctr, 6400, ctr_b,
                                                    out, nullptr, nullptr, nullptr, ytr, NY);
    gemm_hc<4,0><<<dim3(64, 50), thr, SMEM_BYTES>>>(hz, 256, Wcti, 6400, cti_b,
                                                    out + 128, nullptr, nullptr, nullptr, yti, NY);
    // Dt fused with einsum('byu,bu->by')
    gemm_hc<5,0><<<dim3(64, 13), thr, SMEM_BYTES>>>(hz, 256, Wdtw, 1600, dtw_b,
                                                    ut, dt, nullptr, nullptr, ytd, NY);
    yt_combine_kernel<<<(BATCH * NY + 255) / 256, 256>>>(out);
}

// round 10
// speedup vs baseline: 7.9352x; 1.0009x over previous
#include <cuda_runtime.h>
#include <cuda_fp16.h>
#include <math.h>
#include <stdint.h>

#define BATCH  8192
#define LATENT 256
#define CD     128
#define UDIM   32
#define NY     50
#define NTH    256

// ---------------- scratch (static device globals; no allocation) ----------------
__device__ __half g_A0 [BATCH * 320];
__device__ __half g_W0 [256 * 320];
__device__ __half g_W1 [256 * 256];
__device__ __half g_W2 [256 * 256];
__device__ __half g_Wao[256 * 256];
__device__ float  g_Bao[256];
__device__ __half g_Wbtr[4096 * 256];
__device__ __half g_Wbti[4096 * 256];
__device__ __half g_Wctr[6400 * 256];
__device__ __half g_Wcti[6400 * 256];
__device__ __half g_Wdtw[1600 * 256];
__device__ __half g_x1[BATCH * LATENT];
__device__ __half g_x2[BATCH * LATENT];
__device__ __half g_hz[BATCH * LATENT];
__device__ float g_ao[BATCH * LATENT];
__device__ float g_zincr_r[BATCH * CD];
__device__ float g_zincr_i[BATCH * CD];
__device__ float g_ytr[BATCH * NY];
__device__ float g_yti[BATCH * NY];
__device__ float g_ytd[BATCH * NY];

// ---------------- PTX helpers ----------------
__device__ __forceinline__ void ldsm4(uint32_t& a0, uint32_t& a1, uint32_t& a2, uint32_t& a3,
                                      uint32_t addr) {
    asm volatile("ldmatrix.sync.aligned.m8n8.x4.shared.b16 {%0,%1,%2,%3}, [%4];"
                 : "=r"(a0), "=r"(a1), "=r"(a2), "=r"(a3) : "r"(addr));
}
__device__ __forceinline__ void mma_f16(float* c,
                                        uint32_t a0, uint32_t a1, uint32_t a2, uint32_t a3,
                                        uint32_t b0, uint32_t b1) {
    asm volatile(
        "mma.sync.aligned.m16n8k16.row.col.f32.f16.f16.f32 "
        "{%0,%1,%2,%3},{%4,%5,%6,%7},{%8,%9},{%0,%1,%2,%3};"
        : "+f"(c[0]), "+f"(c[1]), "+f"(c[2]), "+f"(c[3])
        : "r"(a0), "r"(a1), "r"(a2), "r"(a3), "r"(b0), "r"(b1));
}
__device__ __forceinline__ void cp16(uint32_t dst, const void* src, int sz) {
    asm volatile("cp.async.cg.shared.global [%0], [%1], 16, %2;"
                 :: "r"(dst), "l"(src), "r"(sz));
}

// ---------------- prep: convert all GEMM operands to fp16 ----------------
#define E_A0  (BATCH * 320)
#define E_W0  (E_A0  + 256 * 320)
#define E_W1  (E_W0  + 65536)
#define E_W2  (E_W1  + 65536)
#define E_WAO (E_W2  + 65536)
#define E_BAO (E_WAO + 256)
#define E_BTR (E_BAO + 4096 * 256)
#define E_BTI (E_BTR + 4096 * 256)
#define E_CTR (E_BTI + 6400 * 256)
#define E_CTI (E_CTR + 6400 * 256)
#define E_DTW (E_CTI + 1600 * 256)

__global__ void prep_kernel(const float* __restrict__ zt, const float* __restrict__ dt,
                            const float* __restrict__ ut,
                            const float* __restrict__ sw0, const float* __restrict__ sw1,
                            const float* __restrict__ sw2,
                            const float* __restrict__ aw, const float* __restrict__ ab,
                            const float* __restrict__ ow, const float* __restrict__ ob,
                            const float* __restrict__ btr, const float* __restrict__ bti,
                            const float* __restrict__ ctr, const float* __restrict__ cti,
                            const float* __restrict__ dtw)
{
    for (int idx = blockIdx.x * blockDim.x + threadIdx.x; idx < E_DTW;
         idx += gridDim.x * blockDim.x) {
        if (idx < E_A0) {
            int m = idx / 320, c = idx % 320;
            float v = 0.f;
            if (c < 256)       v = zt[m * 256 + c];
            else if (c < 288)  v = ut[m * UDIM + (c - 256)];
            else if (c == 288) v = dt[m];
            g_A0[idx] = __float2half(v);
        } else if (idx < E_W0) {
            int j = idx - E_A0;
            int r = j / 320, c = j % 320;
            g_W0[j] = __float2half((c < 289) ? sw0[r * 289 + c] : 0.f);
        } else if (idx < E_W1) {
            int j = idx - E_W0;  g_W1[j] = __float2half(sw1[j]);
        } else if (idx < E_W2) {
            int j = idx - E_W1;  g_W2[j] = __float2half(sw2[j]);
        } else if (idx < E_WAO) {
            int j = idx - E_W2;
            g_Wao[j] = __float2half((j < 128 * 256) ? aw[j] : ow[j - 128 * 256]);
        } else if (idx < E_BAO) {
            int j = idx - E_WAO;
            g_Bao[j] = (j < 128) ? ab[j] : ob[j - 128];
        } else if (idx < E_BTR) {
            int j = idx - E_BAO; g_Wbtr[j] = __float2half(btr[j]);
        } else if (idx < E_BTI) {
            int j = idx - E_BTR; g_Wbti[j] = __float2half(bti[j]);
        } else if (idx < E_CTR) {
            int j = idx - E_BTI; g_Wctr[j] = __float2half(ctr[j]);
        } else if (idx < E_CTI) {
            int j = idx - E_CTR; g_Wcti[j] = __float2half(cti[j]);
        } else {
            int j = idx - E_CTI; g_Wdtw[j] = __float2half(dtw[j]);
        }
    }
}

// ---------------------------------------------------------------------------
// fp16 m16n8k16 fused GEMM, 256 threads, templated M-tile (MT frags/warp).
// CTA tile (MT*32) x 128, BK=64, 3-stage cp.async, 1 sync/chunk.
// 8 warps as 2(m) x 4(n); warp tile (MT*16) x 32.
//   MODE 1: BN(eval)+ReLU -> half out, ldc=256
//   MODE 2: +bias -> half out (OUTH=1) or float out (OUTH=0), ldc=256
//   MODE 3: +bias, contract 32-col u-group/warp with ut*dt, ldc=128
//   MODE 4: +bias, contract tile's 128 cols with zv (1 y/tile), ldc=NY
//   MODE 5: MODE 3 with group bounds (Dt), ldc=NY
// ---------------------------------------------------------------------------
template <int MODE, int OUTH, int MT>
__global__ __launch_bounds__(NTH, 2)
void gemm_hc(const __half* __restrict__ A, int K,
             const __half* __restrict__ W, int N,
             const float* __restrict__ bias,
             const float* __restrict__ p0,   // ut (3/5) | zv base (4)
             const float* __restrict__ p1,   // dt (3/5)
             const float* __restrict__ p2,   // bn gamma (1)
             const float* __restrict__ p3,   // bn beta  (1)
             void* __restrict__ Cout, int ldc)
{
    constexpr int MTILE = MT * 32;                 // 64 or 128
    constexpr int STAGE_BYTES = (MTILE + 128) * 128;
    constexpr int STGW = STAGE_BYTES / 4;
    constexpr int CTRLW = 3 * STGW;

    extern __shared__ float sm[];
    const uint32_t* smb = (const uint32_t*)sm;
    float* sbias = sm + CTRLW;
    float* sg    = sbias + 128;
    float* sbe   = sg + 128;
    float* red   = sbe + 128;                      // MTILE*4 floats (MODE 4)

    const int tid  = threadIdx.x;
    const int lane = tid & 31;
    const int warp = tid >> 5;
    const int m0 = blockIdx.x * MTILE;
    const int n0 = blockIdx.y * 128;
    const int wm = warp >> 2;           // 0..1  (MTILE/2 rows each)
    const int wn = warp & 3;            // 0..3  (32 cols each)
    const int gq = lane >> 2;
    const int tq = lane & 3;
    const uint32_t smu = (uint32_t)__cvta_generic_to_shared(sm);

    if (tid < 128) {
        int n = n0 + tid;
        sbias[tid] = (n < N) ? bias[n] : 0.f;
        if (MODE == 1) {
            sg[tid]  = p2[n] * rsqrtf(1.f + 1e-5f);
            sbe[tid] = p3[n];
        }
    }

    float acc[MT][4][4];
#pragma unroll
    for (int i = 0; i < MT; i++)
#pragma unroll
        for (int j = 0; j < 4; j++)
#pragma unroll
            for (int r = 0; r < 4; r++) acc[i][j][r] = 0.f;

    // ldmatrix lane constants
    const int row_off = lane & 15;
    const int hi = lane >> 4;
    uint32_t abyte[MT]; int arx[MT];
#pragma unroll
    for (int mt = 0; mt < MT; mt++) {
        int r = wm * (MT * 16) + mt * 16 + row_off;
        abyte[mt] = smu + (uint32_t)(r * 128);
        arx[mt] = r & 7;
    }
    int bidx[4], bx[4];
#pragma unroll
    for (int nt = 0; nt < 4; nt++) {
        int n = wn * 32 + nt * 8 + gq;
        bidx[nt] = n * 32 + tq;         // 32 words per 128B row
        bx[nt] = n & 7;
    }

    auto issue = [&](int kc, int s) {
        const int tot = (MTILE + 128) * 8;
#pragma unroll
        for (int i = tid; i < tot; i += NTH) {
            int r = i >> 3, g16 = i & 7;
            uint32_t dst; const __half* src; int sz = 16;
            if (r < MTILE) {
                dst = smu + (uint32_t)(s * STAGE_BYTES + r * 128 + ((g16 ^ (r & 7)) << 4));
                src = A + (size_t)(m0 + r) * K + kc * 64 + g16 * 8;
            } else {
                int rb = r - MTILE;
                dst = smu + (uint32_t)(s * STAGE_BYTES + MTILE * 128 + rb * 128 + ((g16 ^ (rb & 7)) << 4));
                int n = n0 + rb;
                if (n < N) src = W + (size_t)n * K + kc * 64 + g16 * 8;
                else { src = W; sz = 0; }
            }
            cp16(dst, src, sz);
        }
        asm volatile("cp.async.commit_group;" ::: "memory");
    };

    auto compute = [&](int s) {
        const uint32_t sa = (uint32_t)(s * STAGE_BYTES);
        const int sbf = s * STGW + MTILE * 32;     // B region word offset
#pragma unroll
        for (int ks = 0; ks < 4; ks++) {           // 4 x k16 per 64-k chunk
            uint32_t bf0[4], bf1[4];
#pragma unroll
            for (int nt = 0; nt < 4; nt++) {
                bf0[nt] = smb[sbf + bidx[nt] + (((2 * ks)     ^ bx[nt]) << 2)];
                bf1[nt] = smb[sbf + bidx[nt] + (((2 * ks + 1) ^ bx[nt]) << 2)];
            }
            const int ga = 2 * ks + hi;
#pragma unroll
            for (int mt = 0; mt < MT; mt++) {
                uint32_t a0, a1, a2, a3;
                ldsm4(a0, a1, a2, a3, abyte[mt] + sa + (uint32_t)((ga ^ arx[mt]) << 4));
#pragma unroll
                for (int nt = 0; nt < 4; nt++)
                    mma_f16(acc[mt][nt], a0, a1, a2, a3, bf0[nt], bf1[nt]);
            }
        }
    };

    const int NC = K >> 6;                         // 64 k per chunk
    issue(0, 0);
    issue(1, 1);
    for (int kc = 0; kc < NC; kc++) {
        asm volatile("cp.async.wait_group 1;" ::: "memory");
        __syncthreads();
        int pf = kc + 2;
        if (pf < NC) issue(pf, pf % 3);
        else asm volatile("cp.async.commit_group;" ::: "memory");
        compute(kc % 3);
    }

    // ---------------- epilogues ----------------
    // acc r=h*2+p -> m = m0+wm*(MT*16)+mt*16+gq+h*8 ; col nl = wn*32+nt*8+tq*2+p
    if (MODE <= 2) {
#pragma unroll
        for (int nt = 0; nt < 4; nt++)
#pragma unroll
            for (int p = 0; p < 2; p++) {
                int nl = wn * 32 + nt * 8 + tq * 2 + p;
                int n = n0 + nl;
                float bi = sbias[nl];
                float gg = (MODE == 1) ? sg[nl] : 0.f;
                float bb = (MODE == 1) ? sbe[nl] : 0.f;
#pragma unroll
                for (int mt = 0; mt < MT; mt++)
#pragma unroll
                    for (int h = 0; h < 2; h++) {
                        int m = m0 + wm * (MT * 16) + mt * 16 + gq + h * 8;
                        float v = acc[mt][nt][h * 2 + p] + bi;
                        if (MODE == 1) v = fmaxf(v * gg + bb, 0.f);
                        if (OUTH) ((__half*)Cout)[(size_t)m * ldc + n] = __float2half(v);
                        else      ((float*)Cout)[(size_t)m * ldc + n] = v;
                    }
            }
    } else if (MODE == 3 || MODE == 5) {
        const int gcol = blockIdx.y * 4 + wn;
        const bool gvalid = (MODE == 3) || (gcol < NY);
        float* Cf = (float*)Cout;
#pragma unroll
        for (int mt = 0; mt < MT; mt++)
#pragma unroll
            for (int h = 0; h < 2; h++) {
                int m = m0 + wm * (MT * 16) + mt * 16 + gq + h * 8;
                float s = 0.f;
#pragma unroll
                for (int nt = 0; nt < 4; nt++)
#pragma unroll
                    for (int p = 0; p < 2; p++) {
                        int u = nt * 8 + tq * 2 + p;
                        s += (acc[mt][nt][h * 2 + p] + sbias[wn * 32 + u])
                             * p0[(size_t)m * UDIM + u];
                    }
                s += __shfl_xor_sync(0xffffffffu, s, 1);
                s += __shfl_xor_sync(0xffffffffu, s, 2);
                if (tq == 0 && gvalid)
                    Cf[(size_t)m * ldc + gcol] = s * p1[m];
            }
    } else {  // MODE 4: whole 128-col tile = one y; contract with zv
        float* Cf = (float*)Cout;
#pragma unroll
        for (int mt = 0; mt < MT; mt++)
#pragma unroll
            for (int h = 0; h < 2; h++) {
                int rl = wm * (MT * 16) + mt * 16 + gq + h * 8;
                int m = m0 + rl;
                float s = 0.f;
#pragma unroll
                for (int nt = 0; nt < 4; nt++)
#pragma unroll
                    for (int p = 0; p < 2; p++) {
                        int cl = wn * 32 + nt * 8 + tq * 2 + p;
                        s += (acc[mt][nt][h * 2 + p] + sbias[cl])
                             * p0[(size_t)m * 256 + cl];
                    }
                s += __shfl_xor_sync(0xffffffffu, s, 1);
                s += __shfl_xor_sync(0xffffffffu, s, 2);
                if (tq == 0)
                    red[rl * 4 + wn] = s;
            }
        __syncthreads();
        if (tid < MTILE) {
            float s = red[tid * 4] + red[tid * 4 + 1]
                    + red[tid * 4 + 2] + red[tid * 4 + 3];
            Cf[(size_t)(m0 + tid) * ldc + blockIdx.y] = s;
        }
    }
}

// z_next = exp(-softplus(a) + i*omega) * z + zincr
__global__ void znext_kernel(const float* __restrict__ zt, float* __restrict__ out)
{
    int idx = blockIdx.x * blockDim.x + threadIdx.x;
    if (idx >= BATCH * CD) return;
    int m = idx >> 7, c = idx & 127;
    float a = g_ao[m * 256 + c];
    float w = g_ao[m * 256 + 128 + c];
    float ea = 1.f / (1.f + expf(a));
    float lr = ea * cosf(w);
    float li = ea * sinf(w);
    float zr = zt[m * 256 + c];
    float zi = zt[m * 256 + 128 + c];
    out[m * 256 + c]       = lr * zr - li * zi + g_zincr_r[idx];
    out[m * 256 + 128 + c] = lr * zi + li * zr + g_zincr_i[idx];
}

__global__ void yt_combine_kernel(float* __restrict__ out)
{
    int idx = blockIdx.x * blockDim.x + threadIdx.x;
    if (idx >= BATCH * NY) return;
    out[BATCH * LATENT + idx] = g_ytr[idx] - g_yti[idx] + g_ytd[idx];
}

// ================================================================================
extern "C" void kernel_launch(void* const* d_in, const int* in_sizes, int n_in,
                              void* d_out, int out_size)
{
    const float* zt      = (const float*)d_in[0];
    const float* dt      = (const float*)d_in[1];
    const float* ut      = (const float*)d_in[2];
    const float* sel_w0  = (const float*)d_in[3];
    const float* sel_b0  = (const float*)d_in[4];
    const float* sel_g0  = (const float*)d_in[5];
    const float* sel_be0 = (const float*)d_in[6];
    const float* sel_w1  = (const float*)d_in[7];
    const float* sel_b1  = (const float*)d_in[8];
    const float* sel_g1  = (const float*)d_in[9];
    const float* sel_be1 = (const float*)d_in[10];
    const float* sel_w2  = (const float*)d_in[11];
    const float* sel_b2  = (const float*)d_in[12];
    const float* alpha_w = (const float*)d_in[13];
    const float* alpha_b = (const float*)d_in[14];
    const float* omega_w = (const float*)d_in[15];
    const float* omega_b = (const float*)d_in[16];
    const float* btr_w   = (const float*)d_in[17];
    const float* btr_b   = (const float*)d_in[18];
    const float* bti_w   = (const float*)d_in[19];
    const float* bti_b   = (const float*)d_in[20];
    const float* ctr_w   = (const float*)d_in[21];
    const float* ctr_b   = (const float*)d_in[22];
    const float* cti_w   = (const float*)d_in[23];
    const float* cti_b   = (const float*)d_in[24];
    const float* dtw_w   = (const float*)d_in[25];
    const float* dtw_b   = (const float*)d_in[26];
    float* out = (float*)d_out;

    __half *A0, *W0, *W1, *W2, *Wao, *Wbtr, *Wbti, *Wctr, *Wcti, *Wdtw;
    __half *x1, *x2, *hz;
    float *Bao, *ao, *zir, *zii, *ytr, *yti, *ytd;
    cudaGetSymbolAddress((void**)&A0,   g_A0);
    cudaGetSymbolAddress((void**)&W0,   g_W0);
    cudaGetSymbolAddress((void**)&W1,   g_W1);
    cudaGetSymbolAddress((void**)&W2,   g_W2);
    cudaGetSymbolAddress((void**)&Wao,  g_Wao);
    cudaGetSymbolAddress((void**)&Bao,  g_Bao);
    cudaGetSymbolAddress((void**)&Wbtr, g_Wbtr);
    cudaGetSymbolAddress((void**)&Wbti, g_Wbti);
    cudaGetSymbolAddress((void**)&Wctr, g_Wctr);
    cudaGetSymbolAddress((void**)&Wcti, g_Wcti);
    cudaGetSymbolAddress((void**)&Wdtw, g_Wdtw);
    cudaGetSymbolAddress((void**)&x1,  g_x1);
    cudaGetSymbolAddress((void**)&x2,  g_x2);
    cudaGetSymbolAddress((void**)&hz,  g_hz);
    cudaGetSymbolAddress((void**)&ao,  g_ao);
    cudaGetSymbolAddress((void**)&zir, g_zincr_r);
    cudaGetSymbolAddress((void**)&zii, g_zincr_i);
    cudaGetSymbolAddress((void**)&ytr, g_ytr);
    cudaGetSymbolAddress((void**)&yti, g_yti);
    cudaGetSymbolAddress((void**)&ytd, g_ytd);

    const int SMB2 = 3 * (64  + 128) * 128 + 4096;   //  76 KB (MT=2)
    const int SMB4 = 3 * (128 + 128) * 128 + 4096;   // 100 KB (MT=4)
    cudaFuncSetAttribute((const void*)gemm_hc<1,1,2>, cudaFuncAttributeMaxDynamicSharedMemorySize, SMB2);
    cudaFuncSetAttribute((const void*)gemm_hc<2,1,2>, cudaFuncAttributeMaxDynamicSharedMemorySize, SMB2);
    cudaFuncSetAttribute((const void*)gemm_hc<2,0,2>, cudaFuncAttributeMaxDynamicSharedMemorySize, SMB2);
    cudaFuncSetAttribute((const void*)gemm_hc<3,0,4>, cudaFuncAttributeMaxDynamicSharedMemorySize, SMB4);
    cudaFuncSetAttribute((const void*)gemm_hc<4,0,4>, cudaFuncAttributeMaxDynamicSharedMemorySize, SMB4);
    cudaFuncSetAttribute((const void*)gemm_hc<5,0,4>, cudaFuncAttributeMaxDynamicSharedMemorySize, SMB4);

    dim3 thr(NTH);

    prep_kernel<<<2048, 256>>>(zt, dt, ut, sel_w0, sel_w1, sel_w2,
                               alpha_w, alpha_b, omega_w, omega_b,
                               btr_w, bti_w, ctr_w, cti_w, dtw_w);

    // selector MLP — MT=2 tiles (64x128), 256 CTAs -> ~2 CTAs/SM chip-wide
    gemm_hc<1,1,2><<<dim3(128, 2), thr, SMB2>>>(A0, 320, W0, 256, sel_b0,
                                                nullptr, nullptr, sel_g0, sel_be0, x1, 256);
    gemm_hc<1,1,2><<<dim3(128, 2), thr, SMB2>>>(x1, 256, W1, 256, sel_b1,
                                                nullptr, nullptr, sel_g1, sel_be1, x2, 256);
    gemm_hc<2,1,2><<<dim3(128, 2), thr, SMB2>>>(x2, 256, W2, 256, sel_b2,
                                                nullptr, nullptr, nullptr, nullptr, hz, 256);
    // alpha|omega (float out for znext)
    gemm_hc<2,0,2><<<dim3(128, 2), thr, SMB2>>>(hz, 256, Wao, 256, Bao,
                                                nullptr, nullptr, nullptr, nullptr, ao, 256);
    // Bt (real, imag) fused with einsum('bcu,bu->bc') — MT=4
    gemm_hc<3,0,4><<<dim3(64, 32), thr, SMB4>>>(hz, 256, Wbtr, 4096, btr_b,
                                                ut, dt, nullptr, nullptr, zir, CD);
    gemm_hc<3,0,4><<<dim3(64, 32), thr, SMB4>>>(hz, 256, Wbti, 4096, bti_b,
                                                ut, dt, nullptr, nullptr, zii, CD);
    znext_kernel<<<(BATCH * CD) / 256, 256>>>(zt, out);
    // Ct (real, imag) fused with einsum('byc,bc->by') — MT=4
    gemm_hc<4,0,4><<<dim3(64, 50), thr, SMB4>>>(hz, 256, Wctr, 6400, ctr_b,
                                                out, nullptr, nullptr, nullptr, ytr, NY);
    gemm_hc<4,0,4><<<dim3(64, 50), thr, SMB4>>>(hz, 256, Wcti, 6400, cti_b,
                                                out + 128, nullptr, nullptr, nullptr, yti, NY);
    // Dt fused with einsum('byu,bu->by') — MT=4
    gemm_hc<5,0,4><<<dim3(64, 13), thr, SMB4>>>(hz, 256, Wdtw, 1600, dtw_b,
                                                ut, dt, nullptr, nullptr, ytd, NY);
    yt_combine_kernel<<<(BATCH * NY + 255) / 256, 256>>>(out);
}

// round 11
// speedup vs baseline: 8.0997x; 1.0207x over previous
#include <cuda_runtime.h>
#include <cuda_fp16.h>
#include <math.h>
#include <stdint.h>

#define BATCH  8192
#define LATENT 256
#define CD     128
#define UDIM   32
#define NY     50
#define NTH    256

// ---------------- scratch (static device globals; no allocation) ----------------
__device__ __half g_A0 [BATCH * 320];
__device__ __half g_W0 [256 * 320];
__device__ __half g_W1 [256 * 256];
__device__ __half g_W2 [256 * 256];
__device__ __half g_Wao[256 * 256];
__device__ float  g_Bao[256];
__device__ __half g_Wbt[8192 * 256];     // rows 0-4095 btr, 4096-8191 bti
__device__ float  g_Bbt[8192];
__device__ __half g_Wctr[6400 * 256];
__device__ __half g_Wcti[6400 * 256];
__device__ __half g_Wdtw[1600 * 256];
__device__ __half g_x1[BATCH * LATENT];
__device__ __half g_x2[BATCH * LATENT];
__device__ __half g_hz[BATCH * LATENT];
__device__ float g_ao[BATCH * LATENT];
__device__ float g_zincr[BATCH * 256];   // cols 0-127 real incr, 128-255 imag incr
__device__ float g_ytr[BATCH * NY];
__device__ float g_yti[BATCH * NY];
__device__ float g_ytd[BATCH * NY];

// ---------------- PTX helpers ----------------
__device__ __forceinline__ void ldsm4(uint32_t& a0, uint32_t& a1, uint32_t& a2, uint32_t& a3,
                                      uint32_t addr) {
    asm volatile("ldmatrix.sync.aligned.m8n8.x4.shared.b16 {%0,%1,%2,%3}, [%4];"
                 : "=r"(a0), "=r"(a1), "=r"(a2), "=r"(a3) : "r"(addr));
}
__device__ __forceinline__ void mma_f16(float* c,
                                        uint32_t a0, uint32_t a1, uint32_t a2, uint32_t a3,
                                        uint32_t b0, uint32_t b1) {
    asm volatile(
        "mma.sync.aligned.m16n8k16.row.col.f32.f16.f16.f32 "
        "{%0,%1,%2,%3},{%4,%5,%6,%7},{%8,%9},{%0,%1,%2,%3};"
        : "+f"(c[0]), "+f"(c[1]), "+f"(c[2]), "+f"(c[3])
        : "r"(a0), "r"(a1), "r"(a2), "r"(a3), "r"(b0), "r"(b1));
}
__device__ __forceinline__ void cp16(uint32_t dst, const void* src, int sz) {
    asm volatile("cp.async.cg.shared.global [%0], [%1], 16, %2;"
                 :: "r"(dst), "l"(src), "r"(sz));
}

// ---------------- prep: convert all GEMM operands to fp16 ----------------
#define E_A0  (BATCH * 320)
#define E_W0  (E_A0  + 256 * 320)
#define E_W1  (E_W0  + 65536)
#define E_W2  (E_W1  + 65536)
#define E_WAO (E_W2  + 65536)
#define E_BAO (E_WAO + 256)
#define E_WBT (E_BAO + 8192 * 256)
#define E_BBT (E_WBT + 8192)
#define E_CTR (E_BBT + 6400 * 256)
#define E_CTI (E_CTR + 6400 * 256)
#define E_DTW (E_CTI + 1600 * 256)

__global__ void prep_kernel(const float* __restrict__ zt, const float* __restrict__ dt,
                            const float* __restrict__ ut,
                            const float* __restrict__ sw0, const float* __restrict__ sw1,
                            const float* __restrict__ sw2,
                            const float* __restrict__ aw, const float* __restrict__ ab,
                            const float* __restrict__ ow, const float* __restrict__ ob,
                            const float* __restrict__ btr, const float* __restrict__ btr_b,
                            const float* __restrict__ bti, const float* __restrict__ bti_b,
                            const float* __restrict__ ctr, const float* __restrict__ cti,
                            const float* __restrict__ dtw)
{
    for (int idx = blockIdx.x * blockDim.x + threadIdx.x; idx < E_DTW;
         idx += gridDim.x * blockDim.x) {
        if (idx < E_A0) {
            int m = idx / 320, c = idx % 320;
            float v = 0.f;
            if (c < 256)       v = zt[m * 256 + c];
            else if (c < 288)  v = ut[m * UDIM + (c - 256)];
            else if (c == 288) v = dt[m];
            g_A0[idx] = __float2half(v);
        } else if (idx < E_W0) {
            int j = idx - E_A0;
            int r = j / 320, c = j % 320;
            g_W0[j] = __float2half((c < 289) ? sw0[r * 289 + c] : 0.f);
        } else if (idx < E_W1) {
            int j = idx - E_W0;  g_W1[j] = __float2half(sw1[j]);
        } else if (idx < E_W2) {
            int j = idx - E_W1;  g_W2[j] = __float2half(sw2[j]);
        } else if (idx < E_WAO) {
            int j = idx - E_W2;
            g_Wao[j] = __float2half((j < 128 * 256) ? aw[j] : ow[j - 128 * 256]);
        } else if (idx < E_BAO) {
            int j = idx - E_WAO;
            g_Bao[j] = (j < 128) ? ab[j] : ob[j - 128];
        } else if (idx < E_WBT) {
            int j = idx - E_BAO;
            g_Wbt[j] = __float2half((j < 4096 * 256) ? btr[j] : bti[j - 4096 * 256]);
        } else if (idx < E_BBT) {
            int j = idx - E_WBT;
            g_Bbt[j] = (j < 4096) ? btr_b[j] : bti_b[j - 4096];
        } else if (idx < E_CTR) {
            int j = idx - E_BBT; g_Wctr[j] = __float2half(ctr[j]);
        } else if (idx < E_CTI) {
            int j = idx - E_CTR; g_Wcti[j] = __float2half(cti[j]);
        } else {
            int j = idx - E_CTI; g_Wdtw[j] = __float2half(dtw[j]);
        }
    }
}

// ---------------------------------------------------------------------------
// fp16 m16n8k16 fused GEMM, 256 threads, templated M-tile (MT frags/warp).
// CTA tile (MT*32) x 128, BK=64, 3-stage cp.async, 1 sync/chunk.
// Both A and B fragments loaded via ldmatrix (B: 2 x ldsm.x4 per k16-step).
// 8 warps as 2(m) x 4(n); warp tile (MT*16) x 32.
//   MODE 1: BN(eval)+ReLU -> half out, ldc=256
//   MODE 2: +bias -> half out (OUTH=1) or float out (OUTH=0), ldc=256
//   MODE 3: +bias, contract 32-col u-group/warp with ut*dt, ldc by caller
//   MODE 4: +bias, contract tile's 128 cols with zv (1 y/tile), ldc=NY
//   MODE 5: MODE 3 with group bounds (Dt), ldc=NY
// ---------------------------------------------------------------------------
template <int MODE, int OUTH, int MT>
__global__ __launch_bounds__(NTH, 2)
void gemm_hc(const __half* __restrict__ A, int K,
             const __half* __restrict__ W, int N,
             const float* __restrict__ bias,
             const float* __restrict__ p0,   // ut (3/5) | zv base (4)
             const float* __restrict__ p1,   // dt (3/5)
             const float* __restrict__ p2,   // bn gamma (1)
             const float* __restrict__ p3,   // bn beta  (1)
             void* __restrict__ Cout, int ldc)
{
    constexpr int MTILE = MT * 32;                 // 64 or 128
    constexpr int STAGE_BYTES = (MTILE + 128) * 128;
    constexpr int STGW = STAGE_BYTES / 4;
    constexpr int CTRLW = 3 * STGW;

    extern __shared__ float sm[];
    float* sbias = sm + CTRLW;
    float* sg    = sbias + 128;
    float* sbe   = sg + 128;
    float* red   = sbe + 128;                      // MTILE*4 floats (MODE 4)

    const int tid  = threadIdx.x;
    const int lane = tid & 31;
    const int warp = tid >> 5;
    const int m0 = blockIdx.x * MTILE;
    const int n0 = blockIdx.y * 128;
    const int wm = warp >> 2;           // 0..1  (MTILE/2 rows each)
    const int wn = warp & 3;            // 0..3  (32 cols each)
    const int gq = lane >> 2;
    const int tq = lane & 3;
    const uint32_t smu = (uint32_t)__cvta_generic_to_shared(sm);

    if (tid < 128) {
        int n = n0 + tid;
        sbias[tid] = (n < N) ? bias[n] : 0.f;
        if (MODE == 1) {
            sg[tid]  = p2[n] * rsqrtf(1.f + 1e-5f);
            sbe[tid] = p3[n];
        }
    }

    float acc[MT][4][4];
#pragma unroll
    for (int i = 0; i < MT; i++)
#pragma unroll
        for (int j = 0; j < 4; j++)
#pragma unroll
            for (int r = 0; r < 4; r++) acc[i][j][r] = 0.f;

    // A ldmatrix lane constants
    const int row_off = lane & 15;
    const int hi = lane >> 4;
    uint32_t abyte[MT]; int arx[MT];
#pragma unroll
    for (int mt = 0; mt < MT; mt++) {
        int r = wm * (MT * 16) + mt * 16 + row_off;
        abyte[mt] = smu + (uint32_t)(r * 128);
        arx[mt] = r & 7;
    }
    // B ldmatrix lane constants: ldsm.x4 call1 covers (nt=0,1)x(g=2ks,2ks+1),
    // call2 covers (nt=2,3). Lane 8*mi+r supplies row (wn*32 + nt*8 + r) at
    // physical granule ((2ks + (mi&1)) ^ r) -- identical bits to the scalar path.
    const int brx = lane & 7;
    const int gpx = (lane >> 3) & 1;
    const uint32_t bb1 = smu + (uint32_t)((MTILE + wn * 32 + (lane >> 4) * 8 + brx) * 128);
    const uint32_t bb2 = bb1 + 16 * 128;

    auto issue = [&](int kc, int s) {
        const int tot = (MTILE + 128) * 8;
#pragma unroll
        for (int i = tid; i < tot; i += NTH) {
            int r = i >> 3, g16 = i & 7;
            uint32_t dst; const __half* src; int sz = 16;
            if (r < MTILE) {
                dst = smu + (uint32_t)(s * STAGE_BYTES + r * 128 + ((g16 ^ (r & 7)) << 4));
                src = A + (size_t)(m0 + r) * K + kc * 64 + g16 * 8;
            } else {
                int rb = r - MTILE;
                dst = smu + (uint32_t)(s * STAGE_BYTES + MTILE * 128 + rb * 128 + ((g16 ^ (rb & 7)) << 4));
                int n = n0 + rb;
                if (n < N) src = W + (size_t)n * K + kc * 64 + g16 * 8;
                else { src = W; sz = 0; }
            }
            cp16(dst, src, sz);
        }
        asm volatile("cp.async.commit_group;" ::: "memory");
    };

    auto compute = [&](int s) {
        const uint32_t sa = (uint32_t)(s * STAGE_BYTES);
#pragma unroll
        for (int ks = 0; ks < 4; ks++) {           // 4 x k16 per 64-k chunk
            uint32_t bf0[4], bf1[4];
            const uint32_t gx = (uint32_t)(((2 * ks + gpx) ^ brx) << 4);
            ldsm4(bf0[0], bf1[0], bf0[1], bf1[1], bb1 + sa + gx);
            ldsm4(bf0[2], bf1[2], bf0[3], bf1[3], bb2 + sa + gx);
            const int ga = 2 * ks + hi;
#pragma unroll
            for (int mt = 0; mt < MT; mt++) {
                uint32_t a0, a1, a2, a3;
                ldsm4(a0, a1, a2, a3, abyte[mt] + sa + (uint32_t)((ga ^ arx[mt]) << 4));
#pragma unroll
                for (int nt = 0; nt < 4; nt++)
                    mma_f16(acc[mt][nt], a0, a1, a2, a3, bf0[nt], bf1[nt]);
            }
        }
    };

    const int NC = K >> 6;                         // 64 k per chunk
    issue(0, 0);
    issue(1, 1);
    for (int kc = 0; kc < NC; kc++) {
        asm volatile("cp.async.wait_group 1;" ::: "memory");
        __syncthreads();
        int pf = kc + 2;
        if (pf < NC) issue(pf, pf % 3);
        else asm volatile("cp.async.commit_group;" ::: "memory");
        compute(kc % 3);
    }

    // ---------------- epilogues ----------------
    // acc r=h*2+p -> m = m0+wm*(MT*16)+mt*16+gq+h*8 ; col nl = wn*32+nt*8+tq*2+p
    if (MODE <= 2) {
#pragma unroll
        for (int nt = 0; nt < 4; nt++)
#pragma unroll
            for (int p = 0; p < 2; p++) {
                int nl = wn * 32 + nt * 8 + tq * 2 + p;
                int n = n0 + nl;
                float bi = sbias[nl];
                float gg = (MODE == 1) ? sg[nl] : 0.f;
                float bb = (MODE == 1) ? sbe[nl] : 0.f;
#pragma unroll
                for (int mt = 0; mt < MT; mt++)
#pragma unroll
                    for (int h = 0; h < 2; h++) {
                        int m = m0 + wm * (MT * 16) + mt * 16 + gq + h * 8;
                        float v = acc[mt][nt][h * 2 + p] + bi;
                        if (MODE == 1) v = fmaxf(v * gg + bb, 0.f);
                        if (OUTH) ((__half*)Cout)[(size_t)m * ldc + n] = __float2half(v);
                        else      ((float*)Cout)[(size_t)m * ldc + n] = v;
                    }
            }
    } else if (MODE == 3 || MODE == 5) {
        const int gcol = blockIdx.y * 4 + wn;
        const bool gvalid = (MODE == 3) || (gcol < NY);
        float* Cf = (float*)Cout;
#pragma unroll
        for (int mt = 0; mt < MT; mt++)
#pragma unroll
            for (int h = 0; h < 2; h++) {
                int m = m0 + wm * (MT * 16) + mt * 16 + gq + h * 8;
                float s = 0.f;
#pragma unroll
                for (int nt = 0; nt < 4; nt++)
#pragma unroll
                    for (int p = 0; p < 2; p++) {
                        int u = nt * 8 + tq * 2 + p;
                        s += (acc[mt][nt][h * 2 + p] + sbias[wn * 32 + u])
                             * p0[(size_t)m * UDIM + u];
                    }
                s += __shfl_xor_sync(0xffffffffu, s, 1);
                s += __shfl_xor_sync(0xffffffffu, s, 2);
                if (tq == 0 && gvalid)
                    Cf[(size_t)m * ldc + gcol] = s * p1[m];
            }
    } else {  // MODE 4: whole 128-col tile = one y; contract with zv
        float* Cf = (float*)Cout;
#pragma unroll
        for (int mt = 0; mt < MT; mt++)
#pragma unroll
            for (int h = 0; h < 2; h++) {
                int rl = wm * (MT * 16) + mt * 16 + gq + h * 8;
                int m = m0 + rl;
                float s = 0.f;
#pragma unroll
                for (int nt = 0; nt < 4; nt++)
#pragma unroll
                    for (int p = 0; p < 2; p++) {
                        int cl = wn * 32 + nt * 8 + tq * 2 + p;
                        s += (acc[mt][nt][h * 2 + p] + sbias[cl])
                             * p0[(size_t)m * 256 + cl];
                    }
                s += __shfl_xor_sync(0xffffffffu, s, 1);
                s += __shfl_xor_sync(0xffffffffu, s, 2);
                if (tq == 0)
                    red[rl * 4 + wn] = s;
            }
        __syncthreads();
        if (tid < MTILE) {
            float s = red[tid * 4] + red[tid * 4 + 1]
                    + red[tid * 4 + 2] + red[tid * 4 + 3];
            Cf[(size_t)(m0 + tid) * ldc + blockIdx.y] = s;
        }
    }
}

// z_next = exp(-softplus(a) + i*omega) * z + zincr   (zincr = [re | im] cols)
__global__ void znext_kernel(const float* __restrict__ zt, float* __restrict__ out)
{
    int idx = blockIdx.x * blockDim.x + threadIdx.x;
    if (idx >= BATCH * CD) return;
    int m = idx >> 7, c = idx & 127;
    float a = g_ao[m * 256 + c];
    float w = g_ao[m * 256 + 128 + c];
    float ea = 1.f / (1.f + expf(a));
    float lr = ea * cosf(w);
    float li = ea * sinf(w);
    float zr = zt[m * 256 + c];
    float zi = zt[m * 256 + 128 + c];
    out[m * 256 + c]       = lr * zr - li * zi + g_zincr[m * 256 + c];
    out[m * 256 + 128 + c] = lr * zi + li * zr + g_zincr[m * 256 + 128 + c];
}

__global__ void yt_combine_kernel(float* __restrict__ out)
{
    int idx = blockIdx.x * blockDim.x + threadIdx.x;
    if (idx >= BATCH * NY) return;
    out[BATCH * LATENT + idx] = g_ytr[idx] - g_yti[idx] + g_ytd[idx];
}

// ================================================================================
extern "C" void kernel_launch(void* const* d_in, const int* in_sizes, int n_in,
                              void* d_out, int out_size)
{
    const float* zt      = (const float*)d_in[0];
    const float* dt      = (const float*)d_in[1];
    const float* ut      = (const float*)d_in[2];
    const float* sel_w0  = (const float*)d_in[3];
    const float* sel_b0  = (const float*)d_in[4];
    const float* sel_g0  = (const float*)d_in[5];
    const float* sel_be0 = (const float*)d_in[6];
    const float* sel_w1  = (const float*)d_in[7];
    const float* sel_b1  = (const float*)d_in[8];
    const float* sel_g1  = (const float*)d_in[9];
    const float* sel_be1 = (const float*)d_in[10];
    const float* sel_w2  = (const float*)d_in[11];
    const float* sel_b2  = (const float*)d_in[12];
    const float* alpha_w = (const float*)d_in[13];
    const float* alpha_b = (const float*)d_in[14];
    const float* omega_w = (const float*)d_in[15];
    const float* omega_b = (const float*)d_in[16];
    const float* btr_w   = (const float*)d_in[17];
    const float* btr_b   = (const float*)d_in[18];
    const float* bti_w   = (const float*)d_in[19];
    const float* bti_b   = (const float*)d_in[20];
    const float* ctr_w   = (const float*)d_in[21];
    const float* ctr_b   = (const float*)d_in[22];
    const float* cti_w   = (const float*)d_in[23];
    const float* cti_b   = (const float*)d_in[24];
    const float* dtw_w   = (const float*)d_in[25];
    const float* dtw_b   = (const float*)d_in[26];
    float* out = (float*)d_out;

    __half *A0, *W0, *W1, *W2, *Wao, *Wbt, *Wctr, *Wcti, *Wdtw;
    __half *x1, *x2, *hz;
    float *Bao, *Bbt, *ao, *zincr, *ytr, *yti, *ytd;
    cudaGetSymbolAddress((void**)&A0,   g_A0);
    cudaGetSymbolAddress((void**)&W0,   g_W0);
    cudaGetSymbolAddress((void**)&W1,   g_W1);
    cudaGetSymbolAddress((void**)&W2,   g_W2);
    cudaGetSymbolAddress((void**)&Wao,  g_Wao);
    cudaGetSymbolAddress((void**)&Bao,  g_Bao);
    cudaGetSymbolAddress((void**)&Wbt,  g_Wbt);
    cudaGetSymbolAddress((void**)&Bbt,  g_Bbt);
    cudaGetSymbolAddress((void**)&Wctr, g_Wctr);
    cudaGetSymbolAddress((void**)&Wcti, g_Wcti);
    cudaGetSymbolAddress((void**)&Wdtw, g_Wdtw);
    cudaGetSymbolAddress((void**)&x1,  g_x1);
    cudaGetSymbolAddress((void**)&x2,  g_x2);
    cudaGetSymbolAddress((void**)&hz,  g_hz);
    cudaGetSymbolAddress((void**)&ao,  g_ao);
    cudaGetSymbolAddress((void**)&zincr, g_zincr);
    cudaGetSymbolAddress((void**)&ytr, g_ytr);
    cudaGetSymbolAddress((void**)&yti, g_yti);
    cudaGetSymbolAddress((void**)&ytd, g_ytd);

    const int SMB2 = 3 * (64  + 128) * 128 + 4096;   //  76 KB (MT=2)
    const int SMB4 = 3 * (128 + 128) * 128 + 4096;   // 100 KB (MT=4)
    cudaFuncSetAttribute((const void*)gemm_hc<1,1,2>, cudaFuncAttributeMaxDynamicSharedMemorySize, SMB2);
    cudaFuncSetAttribute((const void*)gemm_hc<2,1,2>, cudaFuncAttributeMaxDynamicSharedMemorySize, SMB2);
    cudaFuncSetAttribute((const void*)gemm_hc<2,0,2>, cudaFuncAttributeMaxDynamicSharedMemorySize, SMB2);
    cudaFuncSetAttribute((const void*)gemm_hc<3,0,4>, cudaFuncAttributeMaxDynamicSharedMemorySize, SMB4);
    cudaFuncSetAttribute((const void*)gemm_hc<4,0,4>, cudaFuncAttributeMaxDynamicSharedMemorySize, SMB4);
    cudaFuncSetAttribute((const void*)gemm_hc<5,0,4>, cudaFuncAttributeMaxDynamicSharedMemorySize, SMB4);

    dim3 thr(NTH);

    prep_kernel<<<2048, 256>>>(zt, dt, ut, sel_w0, sel_w1, sel_w2,
                               alpha_w, alpha_b, omega_w, omega_b,
                               btr_w, btr_b, bti_w, bti_b,
                               ctr_w, cti_w, dtw_w);

    // selector MLP — MT=2 tiles (64x128)
    gemm_hc<1,1,2><<<dim3(128, 2), thr, SMB2>>>(A0, 320, W0, 256, sel_b0,
                                                nullptr, nullptr, sel_g0, sel_be0, x1, 256);
    gemm_hc<1,1,2><<<dim3(128, 2), thr, SMB2>>>(x1, 256, W1, 256, sel_b1,
                                                nullptr, nullptr, sel_g1, sel_be1, x2, 256);
    gemm_hc<2,1,2><<<dim3(128, 2), thr, SMB2>>>(x2, 256, W2, 256, sel_b2,
                                                nullptr, nullptr, nullptr, nullptr, hz, 256);
    // alpha|omega (float out for znext)
    gemm_hc<2,0,2><<<dim3(128, 2), thr, SMB2>>>(hz, 256, Wao, 256, Bao,
                                                nullptr, nullptr, nullptr, nullptr, ao, 256);
    // Bt merged (real|imag) fused with einsum('bcu,bu->bc') — one launch, MT=4
    gemm_hc<3,0,4><<<dim3(64, 64), thr, SMB4>>>(hz, 256, Wbt, 8192, Bbt,
                                                ut, dt, nullptr, nullptr, zincr, 256);
    znext_kernel<<<(BATCH * CD) / 256, 256>>>(zt, out);
    // Ct (real, imag) fused with einsum('byc,bc->by') — MT=4
    gemm_hc<4,0,4><<<dim3(64, 50), thr, SMB4>>>(hz, 256, Wctr, 6400, ctr_b,
                                                out, nullptr, nullptr, nullptr, ytr, NY);
    gemm_hc<4,0,4><<<dim3(64, 50), thr, SMB4>>>(hz, 256, Wcti, 6400, cti_b,
                                                out + 128, nullptr, nullptr, nullptr, yti, NY);
    // Dt fused with einsum('byu,bu->by') — MT=4
    gemm_hc<5,0,4><<<dim3(64, 13), thr, SMB4>>>(hz, 256, Wdtw, 1600, dtw_b,
                                                ut, dt, nullptr, nullptr, ytd, NY);
    yt_combine_kernel<<<(BATCH * NY + 255) / 256, 256>>>(out);
}